// round 13
// baseline (speedup 1.0000x reference)
#include <cuda_runtime.h>
#include <cuda_bf16.h>
#include <math.h>

#define BNF 0.9999950000374997f
#define BN2F 0.9999900000999990f
#define ATT_SCALE 0.40824829046386301637f

// ---- scratch ----
__device__ float g_covp[16][8][288];
__device__ float g_rfeat[16][48];
__device__ float g_p1[16*32*2000];
__device__ float g_featA[16*250*48];
__device__ float g_featF[16*250*48];
__device__ float g_fused[16*251*48];
__device__ float g_attn[16*251*48];

__device__ __forceinline__ float eluf(float x){ return x > 0.f ? x : (__expf(x) - 1.f); }
__device__ __forceinline__ float geluf(float x){ return 0.5f*x*(1.f+erff(x*0.70710678118654752f)); }

// covariance partial sums: grid(8 chunks,16 b), block 288
__global__ void k_covp(const float* __restrict__ x){
    __shared__ float xs[22*253];
    int b = blockIdx.y, ch = blockIdx.x, tid = threadIdx.x;
    int i=0,j=0;
    if (tid < 253){ int p=tid; while (p >= 22-i){ p -= 22-i; i++; } j = i+p; }
    int c = tid - 253;
    float acc = 0.f;
    for (int tile = 0; tile < 8; tile++){
        int t0 = ch*2000 + tile*250;
        for (int idx = tid; idx < 22*250; idx += 288){
            int cc = idx/250, t = idx%250;
            xs[cc*253+t] = x[(b*22+cc)*16000 + t0 + t];
        }
        __syncthreads();
        if (tid < 253){
            const float* xi = xs + i*253;
            const float* xj = xs + j*253;
            #pragma unroll 5
            for (int t = 0; t < 250; t++) acc += xi[t]*xj[t];
        } else if (tid < 275){
            const float* xc = xs + c*253;
            #pragma unroll 5
            for (int t = 0; t < 250; t++) acc += xc[t];
        }
        __syncthreads();
    }
    if (tid < 275) g_covp[b][ch][tid] = acc;
}

// merged covred + ridge + cholesky + dlog + riem MLP. 1 block, 512 threads (warp = batch)
__global__ void k_spd(const float* __restrict__ rw1, const float* __restrict__ rb1,
                      const float* __restrict__ rw2, const float* __restrict__ rb2){
    __shared__ float A[16*484];
    __shared__ float chs[16][22];
    __shared__ float dlg[16][22];
    __shared__ float trs[16];
    __shared__ float trm;
    int tid = threadIdx.x, w = tid >> 5, lane = tid & 31;
    float* a = A + w*484;
    if (lane < 22){
        float s = 0.f;
        #pragma unroll
        for (int c = 0; c < 8; c++) s += g_covp[w][c][253+lane];
        chs[w][lane] = s;
    }
    __syncwarp();
    for (int p = lane; p < 253; p += 32){
        int i=0,q=p; while (q >= 22-i){ q -= 22-i; i++; } int j = i+q;
        float s = 0.f;
        #pragma unroll
        for (int c = 0; c < 8; c++) s += g_covp[w][c][p];
        float cov = (s - chs[w][i]*chs[w][j]*(1.f/16000.f)) * (1.f/15999.f);
        if (i == j) cov += 1e-5f;
        a[i*22+j] = cov;
        a[j*22+i] = cov;
    }
    __syncwarp();
    if (lane == 0){ float tr=0.f; for (int k=0;k<22;k++) tr += a[k*22+k]; trs[w]=tr; }
    __syncthreads();
    if (tid == 0){ float s=0.f; for (int b=0;b<16;b++) s += trs[b]; trm = s*(0.001f/16.f); }
    __syncthreads();
    if (lane < 22) a[lane*22+lane] += trm;
    __syncwarp();
    for (int jj = 0; jj < 22; jj++){
        float dj = 0.f;
        if (lane == jj){ dj = sqrtf(a[jj*22+jj]); a[jj*22+jj] = dj; }
        dj = __shfl_sync(0xffffffffu, dj, jj);
        if (lane > jj && lane < 22) a[lane*22+jj] /= dj;
        __syncwarp();
        if (lane > jj && lane < 22){
            float lij = a[lane*22+jj];
            for (int k = jj+1; k <= lane; k++) a[lane*22+k] -= lij * a[k*22+jj];
        }
        __syncwarp();
    }
    if (lane < 22){
        float d = a[lane*22+lane];
        dlg[w][lane] = d * logf(fmaxf(d, 1e-10f));
    }
    __syncwarp();
    float hreg[8];
    #pragma unroll
    for (int m = 0; m < 8; m++){
        int h = lane + 32*m;
        float acc = rb1[h];
        #pragma unroll
        for (int i = 0; i < 22; i++){
            int pos = i*22 - (i*(i-1))/2;
            acc += dlg[w][i]*rw1[pos*256 + h];
        }
        hreg[m] = acc > 0.f ? acc : expm1f(acc);
    }
    __syncwarp();
    #pragma unroll
    for (int m = 0; m < 8; m++) a[lane + 32*m] = hreg[m];
    __syncwarp();
    for (int o = lane; o < 48; o += 32){
        float acc = rb2[o];
        #pragma unroll 8
        for (int k = 0; k < 256; k++) acc += a[k]*rw2[k*48+o];
        g_rfeat[w][o] = acc;
    }
}

// fused: channel-mix -> 64-tap FIR -> BN^2 -> elu -> pool8 -> p1. grid(63,16), block 512
__global__ void __launch_bounds__(512, 2) k_conv1f(const float* __restrict__ x,
                                                   const float* __restrict__ dw1w,
                                                   const float* __restrict__ c1w){
    extern __shared__ float sm[];
    float* xs  = sm;            // 22*321 = 7062
    float* ys  = sm + 7062;     // 32*321 = 10272
    float* wsm = sm + 17334;    // 704
    float* cws = sm + 18038;    // 16*65 = 1040   (total 19078 floats)
    int b = blockIdx.y, tid = threadIdx.x;
    int u0 = blockIdx.x*32;
    int T0 = u0*8;
    for (int idx = tid; idx < 22*320; idx += 512){
        int ch = idx/320, m = idx - ch*320;
        int t = T0 - 32 + m;
        xs[ch*321+m] = (t >= 0 && t < 16000) ? x[(b*22+ch)*16000 + t] : 0.f;
    }
    for (int idx = tid; idx < 704; idx += 512) wsm[idx] = dw1w[idx];
    for (int idx = tid; idx < 1024; idx += 512){
        int ic = idx >> 6, k = idx & 63;
        cws[ic*65+k] = c1w[idx];
    }
    __syncthreads();
    for (int idx = tid; idx < 32*320; idx += 512){
        int oc = idx/320, m = idx - oc*320;
        float a = 0.f;
        #pragma unroll
        for (int ch = 0; ch < 22; ch++) a += wsm[oc*22+ch]*xs[ch*321+m];
        ys[oc*321+m] = a;
    }
    __syncthreads();
    int oc = tid & 31, grp = tid >> 5;
    const float* yrow = ys + oc*321;
    const float* cw = cws + (oc>>1)*65;
    #pragma unroll 1
    for (int s2 = 0; s2 < 2; s2++){
        int ul = grp*2 + s2;
        int u = u0 + ul;
        int base = 8*ul;
        float acc[8], yr[8];
        #pragma unroll
        for (int s = 0; s < 8; s++){ acc[s]=0.f; yr[s]=yrow[base+s]; }
        #pragma unroll 8
        for (int k = 0; k < 64; k++){
            float w = cw[k];
            #pragma unroll
            for (int s = 0; s < 8; s++) acc[s] += w*yr[s];
            #pragma unroll
            for (int m = 0; m < 7; m++) yr[m] = yr[m+1];
            yr[7] = yrow[base + k + 8];
        }
        if (u < 2000){
            float p = 0.f;
            #pragma unroll
            for (int s = 0; s < 8; s++) p += eluf(BN2F*acc[s]);
            g_p1[(b*32+oc)*2000 + u] = p*0.125f;
        }
    }
}

// dw2 -> pw -> elu -> pool8 -> featA. grid(16,16), block 256. register-blocked pw GEMM.
__global__ void k_c2(const float* __restrict__ dw2w, const float* __restrict__ pww){
    __shared__ float p1s[32*145];
    __shared__ float qs[32*129];
    __shared__ float pwT[32*49];
    __shared__ float dwt[16*33];
    int b = blockIdx.y, tid = threadIdx.x;
    int u0 = blockIdx.x*16;
    int T0 = u0*8;
    for (int idx = tid; idx < 32*144; idx += 256){
        int oc = idx/144, m = idx%144;
        int t = T0 - 8 + m;
        p1s[oc*145+m] = (t >= 0 && t < 2000) ? g_p1[(b*32+oc)*2000 + t] : 0.f;
    }
    for (int idx = tid; idx < 1536; idx += 256){
        int co = idx/32, ci = idx%32;
        pwT[ci*49+co] = pww[idx];
    }
    for (int idx = tid; idx < 512; idx += 256){
        int oc = idx/16, k = idx%16;
        dwt[k*33+oc] = dw2w[idx];
    }
    __syncthreads();
    for (int v = tid; v < 32*128; v += 256){
        int oc = v & 31, t = v >> 5;
        float a = 0.f;
        #pragma unroll
        for (int k = 0; k < 16; k++) a += dwt[k*33+oc]*p1s[oc*145 + t + k];
        qs[oc*129+t] = a*BNF;
    }
    __syncthreads();
    {
        int cog = tid & 15, ul = tid >> 4;
        int u = u0 + ul;
        int co0 = cog*3;
        float acc[3][8];
        #pragma unroll
        for (int j = 0; j < 3; j++)
            #pragma unroll
            for (int s = 0; s < 8; s++) acc[j][s] = 0.f;
        #pragma unroll 4
        for (int ci = 0; ci < 32; ci++){
            float p0 = pwT[ci*49+co0];
            float p1 = pwT[ci*49+co0+1];
            float p2 = pwT[ci*49+co0+2];
            const float* qr = qs + ci*129 + 8*ul;
            #pragma unroll
            for (int s = 0; s < 8; s++){
                float q = qr[s];
                acc[0][s] += p0*q;
                acc[1][s] += p1*q;
                acc[2][s] += p2*q;
            }
        }
        if (u < 250){
            #pragma unroll
            for (int j = 0; j < 3; j++){
                float p = 0.f;
                #pragma unroll
                for (int s = 0; s < 8; s++) p += eluf(BNF*acc[j][s]);
                g_featA[(b*250+u)*48 + co0 + j] = p*0.125f;
            }
        }
    }
}

// temporal conv branch + residual -> featF. grid(4,16), block 256
__global__ void k_tc(const float* __restrict__ tc1w, const float* __restrict__ tc1b,
                     const float* __restrict__ tc2w, const float* __restrict__ tc2b){
    __shared__ float fa[66*48];
    __shared__ float t1s[24*64];
    int b = blockIdx.y, tid = threadIdx.x;
    int u0 = blockIdx.x*64;
    for (int idx = tid; idx < 66*48; idx += 256){
        int r = idx/48, co = idx%48;
        int u = u0 - 1 + r;
        fa[idx] = (u >= 0 && u < 250) ? g_featA[(b*250+u)*48 + co] : 0.f;
    }
    __syncthreads();
    for (int idx = tid; idx < 24*64; idx += 256){
        int g = idx/64, ul = idx%64;
        if (u0 + ul >= 250) continue;
        float a = tc1b[g];
        #pragma unroll
        for (int ci = 0; ci < 2; ci++)
            #pragma unroll
            for (int k = 0; k < 3; k++)
                a += tc1w[(g*2+ci)*3 + k] * fa[(ul+k)*48 + 2*g + ci];
        t1s[g*64+ul] = geluf(BNF*a);
    }
    __syncthreads();
    for (int idx = tid; idx < 48*64; idx += 256){
        int co = idx % 48, ul = idx / 48;
        int u = u0 + ul;
        if (u >= 250) continue;
        float a = tc2b[co];
        #pragma unroll
        for (int g = 0; g < 24; g++) a += tc2w[co*24+g]*t1s[g*64+ul];
        g_featF[(b*250+u)*48 + co] = fa[(ul+1)*48 + co] + a;
    }
}

// fusion proj + pos_enc. grid(251,16), block 48
__global__ void k_fuse(const float* __restrict__ fproj, const float* __restrict__ pe){
    __shared__ float r[48];
    int n = blockIdx.x, b = blockIdx.y, co = threadIdx.x;
    r[co] = (n == 0) ? g_rfeat[b][co] : g_featF[(b*250 + n - 1)*48 + co];
    __syncthreads();
    float a = pe[n*48 + co];
    #pragma unroll 8
    for (int k = 0; k < 48; k++) a += r[k]*fproj[k*48+co];
    g_fused[(b*251+n)*48 + co] = a;
}

// full transformer layer: LN1+QKV(halo)+band attn+proj+res -> LN2+FFN+res.
// reads 'in', writes 'out'. grid(16,16), block 384, ~158KB dyn smem.
__global__ void k_layer(int l, const float* __restrict__ in, float* __restrict__ out,
                        const float* __restrict__ qw, const float* __restrict__ qb,
                        const float* __restrict__ g1, const float* __restrict__ b1,
                        const float* __restrict__ apw, const float* __restrict__ apb,
                        const float* __restrict__ g2, const float* __restrict__ bb2,
                        const float* __restrict__ fw1, const float* __restrict__ fb1,
                        const float* __restrict__ fw2, const float* __restrict__ fb2){
    extern __shared__ float sm[];
    float* wq   = sm;              // 6912
    float* wp   = wq + 6912;       // 2304
    float* w1s  = wp + 2304;       // 9216
    float* w2s  = w1s + 9216;      // 9216
    float* xf   = w2s + 9216;      // 26*48 = 1248
    float* hn   = xf + 1248;       // 1248
    float* qs   = hn + 1248;       // 26*144 = 3744
    float* sc   = qs + 3744;       // 16*8*12 = 1536
    float* osb  = sc + 1536;       // 768
    float* att  = osb + 768;       // 768
    float* h1   = att + 768;       // 16*192 = 3072
    float* qbs  = h1 + 3072;       // 144
    float* apbs = qbs + 144;       // 48
    float* fb1s = apbs + 48;       // 192
    float* fb2s = fb1s + 192;      // 48   (total 40464 floats)
    int b = blockIdx.y, tid = threadIdx.x;
    int n0 = blockIdx.x*16;
    {
        const float* s1 = qw  + l*48*144;
        const float* s2 = apw + l*48*48;
        const float* s3 = fw1 + l*48*192;
        const float* s4 = fw2 + l*192*48;
        for (int idx = tid; idx < 6912; idx += 384) wq[idx] = s1[idx];
        for (int idx = tid; idx < 2304; idx += 384) wp[idx] = s2[idx];
        for (int idx = tid; idx < 9216; idx += 384){ w1s[idx] = s3[idx]; w2s[idx] = s4[idx]; }
        if (tid < 144) qbs[tid] = qb[l*144 + tid];
        if (tid < 48)  apbs[tid] = apb[l*48 + tid];
        if (tid < 192) fb1s[tid] = fb1[l*192 + tid];
        if (tid < 48)  fb2s[tid] = fb2[l*48 + tid];
    }
    for (int idx = tid; idx < 26*48; idx += 384){
        int r = idx/48, c = idx - r*48;
        int n = n0 - 5 + r;
        xf[idx] = (n >= 0 && n < 251) ? in[(b*251+n)*48 + c] : 0.f;
    }
    __syncthreads();
    // LN1 over 26 rows: 12 warps, rows strided
    {
        int wd = tid >> 5, lane = tid & 31;
        for (int rl = wd; rl < 26; rl += 12){
            float v0 = xf[rl*48 + lane];
            float v1 = (lane < 16) ? xf[rl*48 + 32 + lane] : 0.f;
            float sum = v0 + v1, sq = v0*v0 + v1*v1;
            #pragma unroll
            for (int o = 16; o; o >>= 1){
                sum += __shfl_xor_sync(0xffffffffu, sum, o);
                sq  += __shfl_xor_sync(0xffffffffu, sq, o);
            }
            float m = sum*(1.f/48.f);
            float rinv = rsqrtf(sq*(1.f/48.f) - m*m + 1e-5f);
            hn[rl*48 + lane] = (v0-m)*rinv*g1[l*48+lane] + b1[l*48+lane];
            if (lane < 16) hn[rl*48 + 32 + lane] = (v1-m)*rinv*g1[l*48+32+lane] + b1[l*48+32+lane];
        }
    }
    __syncthreads();
    // QKV for 26 rows
    for (int idx = tid; idx < 26*144; idx += 384){
        int r = idx/144, col = idx - r*144;
        float acc = qbs[col];
        #pragma unroll 8
        for (int k = 0; k < 48; k++) acc += hn[r*48+k]*wq[k*144 + col];
        qs[idx] = acc;
    }
    __syncthreads();
    // scores
    for (int idx = tid; idx < 1408; idx += 384){
        int tl = idx/88, rem = idx - tl*88, h = rem/11, kk = rem - h*11;
        int n = n0 + tl;
        if (n >= 251) continue;
        int kpos = n - 5 + kk;
        if (kpos < 0 || kpos > 250) continue;
        int rq = tl + 5, rk = tl + kk;
        float s = 0.f;
        #pragma unroll
        for (int d = 0; d < 6; d++) s += qs[rq*144 + h*6 + d]*qs[rk*144 + 48 + h*6 + d];
        sc[(tl*8+h)*12 + kk] = s*ATT_SCALE;
    }
    __syncthreads();
    if (tid < 128){
        int tl = tid >> 3, h = tid & 7;
        int n = n0 + tl;
        if (n < 251){
            int klo = (n - 5 < 0) ? 5 - n : 0;
            int khi = (n + 5 > 250) ? 255 - n : 10;
            float mx = -1e30f;
            for (int kk = klo; kk <= khi; kk++) mx = fmaxf(mx, sc[(tl*8+h)*12+kk]);
            float ss = 0.f;
            for (int kk = klo; kk <= khi; kk++){ float e = __expf(sc[(tl*8+h)*12+kk]-mx); sc[(tl*8+h)*12+kk] = e; ss += e; }
            float inv = 1.f/ss;
            float o[6] = {0,0,0,0,0,0};
            for (int kk = klo; kk <= khi; kk++){
                float p = sc[(tl*8+h)*12+kk]*inv;
                int rk = tl + kk;
                #pragma unroll
                for (int d = 0; d < 6; d++) o[d] += p*qs[rk*144 + 96 + h*6 + d];
            }
            #pragma unroll
            for (int d = 0; d < 6; d++) osb[tl*48 + h*6+d] = o[d];
        }
    }
    __syncthreads();
    // out proj + residual -> att (smem)
    for (int idx = tid; idx < 768; idx += 384){
        int rl = idx/48, col = idx - rl*48;
        float acc = apbs[col];
        #pragma unroll 8
        for (int k = 0; k < 48; k++) acc += osb[rl*48+k]*wp[k*48 + col];
        att[idx] = xf[(rl+5)*48 + col] + acc;
    }
    __syncthreads();
    // LN2 over 16 rows (reuse hn[0:768])
    {
        int wd = tid >> 5, lane = tid & 31;
        if (wd < 8){
            #pragma unroll
            for (int s = 0; s < 2; s++){
                int rl = wd*2 + s;
                float v0 = att[rl*48 + lane];
                float v1 = (lane < 16) ? att[rl*48 + 32 + lane] : 0.f;
                float sum = v0 + v1, sq = v0*v0 + v1*v1;
                #pragma unroll
                for (int o = 16; o; o >>= 1){
                    sum += __shfl_xor_sync(0xffffffffu, sum, o);
                    sq  += __shfl_xor_sync(0xffffffffu, sq, o);
                }
                float m = sum*(1.f/48.f);
                float rinv = rsqrtf(sq*(1.f/48.f) - m*m + 1e-5f);
                hn[rl*48 + lane] = (v0-m)*rinv*g2[l*48+lane] + bb2[l*48+lane];
                if (lane < 16) hn[rl*48 + 32 + lane] = (v1-m)*rinv*g2[l*48+32+lane] + bb2[l*48+32+lane];
            }
        }
    }
    __syncthreads();
    // FFN1: 2 groups x 8 rows, 192 cols
    {
        int g = tid/192, col = tid - g*192;
        float acc[8];
        float bv = fb1s[col];
        #pragma unroll
        for (int r = 0; r < 8; r++) acc[r] = bv;
        for (int k = 0; k < 48; k++){
            float wv = w1s[k*192 + col];
            #pragma unroll
            for (int r = 0; r < 8; r++) acc[r] += hn[(g*8+r)*48 + k]*wv;
        }
        #pragma unroll
        for (int r = 0; r < 8; r++) h1[(g*8+r)*192 + col] = geluf(acc[r]);
    }
    __syncthreads();
    // FFN2 + residual -> out
    {
        int col = tid % 48, rg = tid/48;   // 8 groups x 2 rows
        float a0 = fb2s[col], a1 = a0;
        for (int k = 0; k < 192; k++){
            float wv = w2s[k*48 + col];
            a0 += h1[(rg*2  )*192 + k]*wv;
            a1 += h1[(rg*2+1)*192 + k]*wv;
        }
        int nA = n0 + rg*2, nB = nA + 1;
        if (nA < 251) out[(b*251+nA)*48 + col] = att[(rg*2  )*48 + col] + a0;
        if (nB < 251) out[(b*251+nB)*48 + col] = att[(rg*2+1)*48 + col] + a1;
    }
}

// mean over tokens + LN + classifier. grid 16, block 64
__global__ void k_head(const float* __restrict__ cg, const float* __restrict__ cb,
                       const float* __restrict__ cw, const float* __restrict__ cbias,
                       float* __restrict__ out){
    __shared__ float gm[48];
    int b = blockIdx.x, tid = threadIdx.x;
    if (tid < 48){
        float s = 0.f;
        for (int n = 0; n < 251; n++) s += g_fused[(b*251+n)*48 + tid];
        gm[tid] = s*(1.f/251.f);
    }
    __syncthreads();
    if (tid < 4){
        float m = 0.f;
        #pragma unroll 8
        for (int k = 0; k < 48; k++) m += gm[k];
        m *= (1.f/48.f);
        float v = 0.f;
        #pragma unroll 8
        for (int k = 0; k < 48; k++){ float d = gm[k]-m; v += d*d; }
        float rinv = rsqrtf(v*(1.f/48.f) + 1e-5f);
        float a = cbias[tid];
        #pragma unroll 8
        for (int k = 0; k < 48; k++){
            float gn = (gm[k]-m)*rinv*cg[k] + cb[k];
            a += gn*cw[k*4 + tid];
        }
        out[b*4 + tid] = a;
    }
}

#define CONV1F_SMEM (19078*4)
#define LAYER_SMEM  (40464*4)

extern "C" void kernel_launch(void* const* d_in, const int* in_sizes, int n_in,
                              void* d_out, int out_size) {
    const float* x      = (const float*)d_in[0];
    const float* rw1    = (const float*)d_in[1];
    const float* rb1    = (const float*)d_in[2];
    const float* rw2    = (const float*)d_in[3];
    const float* rb2    = (const float*)d_in[4];
    const float* c1w    = (const float*)d_in[5];
    const float* dw1w   = (const float*)d_in[6];
    const float* dw2w   = (const float*)d_in[7];
    const float* pww    = (const float*)d_in[8];
    const float* tc1w   = (const float*)d_in[9];
    const float* tc1b   = (const float*)d_in[10];
    const float* tc2w   = (const float*)d_in[11];
    const float* tc2b   = (const float*)d_in[12];
    const float* fproj  = (const float*)d_in[13];
    const float* pe     = (const float*)d_in[14];
    const float* ln1g   = (const float*)d_in[15];
    const float* ln1b   = (const float*)d_in[16];
    const float* qkvw   = (const float*)d_in[17];
    const float* qkvb   = (const float*)d_in[18];
    const float* apw    = (const float*)d_in[19];
    const float* apb    = (const float*)d_in[20];
    const float* ln2g   = (const float*)d_in[21];
    const float* ln2b   = (const float*)d_in[22];
    const float* fw1    = (const float*)d_in[23];
    const float* fb1    = (const float*)d_in[24];
    const float* fw2    = (const float*)d_in[25];
    const float* fb2    = (const float*)d_in[26];
    const float* clsg   = (const float*)d_in[27];
    const float* clsb   = (const float*)d_in[28];
    const float* clsw   = (const float*)d_in[29];
    const float* clsbias= (const float*)d_in[30];
    float* out = (float*)d_out;

    static int attr_set = 0;
    if (!attr_set){
        cudaFuncSetAttribute(k_conv1f, cudaFuncAttributeMaxDynamicSharedMemorySize, CONV1F_SMEM);
        cudaFuncSetAttribute(k_layer,  cudaFuncAttributeMaxDynamicSharedMemorySize, LAYER_SMEM);
        attr_set = 1;
    }

    k_covp<<<dim3(8,16), 288>>>(x);
    k_spd<<<1, 512>>>(rw1, rb1, rw2, rb2);
    k_conv1f<<<dim3(63,16), 512, CONV1F_SMEM>>>(x, dw1w, c1w);
    k_c2<<<dim3(16,16), 256>>>(dw2w, pww);
    k_tc<<<dim3(4,16), 256>>>(tc1w, tc1b, tc2w, tc2b);
    k_fuse<<<dim3(251,16), 48>>>(fproj, pe);

    float* bufA = nullptr; float* bufB = nullptr;
    cudaGetSymbolAddress((void**)&bufA, g_fused);
    cudaGetSymbolAddress((void**)&bufB, g_attn);
    for (int l = 0; l < 4; l++){
        const float* inb = (l & 1) ? bufB : bufA;
        float* outb      = (l & 1) ? bufA : bufB;
        k_layer<<<dim3(16,16), 384, LAYER_SMEM>>>(l, inb, outb,
            qkvw, qkvb, ln1g, ln1b, apw, apb, ln2g, ln2b, fw1, fb1, fw2, fb2);
    }
    // after 4 layers (even count) final result is in bufA == g_fused
    k_head<<<16, 64>>>(clsg, clsb, clsw, clsbias, out);
}

// round 14
// speedup vs baseline: 1.1582x; 1.1582x over previous
#include <cuda_runtime.h>
#include <cuda_bf16.h>
#include <math.h>

#define BNF 0.9999950000374997f
#define BN2F 0.9999900000999990f
#define ATT_SCALE 0.40824829046386301637f

// ---- scratch ----
__device__ float g_covp[16][8][288];
__device__ float g_rfeat[16][48];
__device__ float g_p1[16*32*2000];
__device__ float g_featA[16*250*48];
__device__ float g_featF[16*250*48];
__device__ float g_fused[16*251*48];
__device__ float g_attn[16*251*48];

__device__ __forceinline__ float eluf(float x){ return x > 0.f ? x : (__expf(x) - 1.f); }
__device__ __forceinline__ float geluf(float x){ return 0.5f*x*(1.f+erff(x*0.70710678118654752f)); }

// covariance partial sums: grid(8 chunks,16 b), block 288
__global__ void k_covp(const float* __restrict__ x){
    __shared__ float xs[22*253];
    int b = blockIdx.y, ch = blockIdx.x, tid = threadIdx.x;
    int i=0,j=0;
    if (tid < 253){ int p=tid; while (p >= 22-i){ p -= 22-i; i++; } j = i+p; }
    int c = tid - 253;
    float acc = 0.f;
    for (int tile = 0; tile < 8; tile++){
        int t0 = ch*2000 + tile*250;
        for (int idx = tid; idx < 22*250; idx += 288){
            int cc = idx/250, t = idx%250;
            xs[cc*253+t] = x[(b*22+cc)*16000 + t0 + t];
        }
        __syncthreads();
        if (tid < 253){
            const float* xi = xs + i*253;
            const float* xj = xs + j*253;
            #pragma unroll 5
            for (int t = 0; t < 250; t++) acc += xi[t]*xj[t];
        } else if (tid < 275){
            const float* xc = xs + c*253;
            #pragma unroll 5
            for (int t = 0; t < 250; t++) acc += xc[t];
        }
        __syncthreads();
    }
    if (tid < 275) g_covp[b][ch][tid] = acc;
}

// merged covred + ridge + cholesky + dlog + riem MLP. 1 block, 512 threads (warp = batch)
__global__ void k_spd(const float* __restrict__ rw1, const float* __restrict__ rb1,
                      const float* __restrict__ rw2, const float* __restrict__ rb2){
    __shared__ float A[16*484];
    __shared__ float chs[16][22];
    __shared__ float dlg[16][22];
    __shared__ float trs[16];
    __shared__ float trm;
    int tid = threadIdx.x, w = tid >> 5, lane = tid & 31;
    float* a = A + w*484;
    if (lane < 22){
        float s = 0.f;
        #pragma unroll
        for (int c = 0; c < 8; c++) s += g_covp[w][c][253+lane];
        chs[w][lane] = s;
    }
    __syncwarp();
    for (int p = lane; p < 253; p += 32){
        int i=0,q=p; while (q >= 22-i){ q -= 22-i; i++; } int j = i+q;
        float s = 0.f;
        #pragma unroll
        for (int c = 0; c < 8; c++) s += g_covp[w][c][p];
        float cov = (s - chs[w][i]*chs[w][j]*(1.f/16000.f)) * (1.f/15999.f);
        if (i == j) cov += 1e-5f;
        a[i*22+j] = cov;
        a[j*22+i] = cov;
    }
    __syncwarp();
    if (lane == 0){ float tr=0.f; for (int k=0;k<22;k++) tr += a[k*22+k]; trs[w]=tr; }
    __syncthreads();
    if (tid == 0){ float s=0.f; for (int b=0;b<16;b++) s += trs[b]; trm = s*(0.001f/16.f); }
    __syncthreads();
    if (lane < 22) a[lane*22+lane] += trm;
    __syncwarp();
    for (int jj = 0; jj < 22; jj++){
        float dj = 0.f;
        if (lane == jj){ dj = sqrtf(a[jj*22+jj]); a[jj*22+jj] = dj; }
        dj = __shfl_sync(0xffffffffu, dj, jj);
        if (lane > jj && lane < 22) a[lane*22+jj] /= dj;
        __syncwarp();
        if (lane > jj && lane < 22){
            float lij = a[lane*22+jj];
            for (int k = jj+1; k <= lane; k++) a[lane*22+k] -= lij * a[k*22+jj];
        }
        __syncwarp();
    }
    if (lane < 22){
        float d = a[lane*22+lane];
        dlg[w][lane] = d * logf(fmaxf(d, 1e-10f));
    }
    __syncwarp();
    float hreg[8];
    #pragma unroll
    for (int m = 0; m < 8; m++){
        int h = lane + 32*m;
        float acc = rb1[h];
        #pragma unroll
        for (int i = 0; i < 22; i++){
            int pos = i*22 - (i*(i-1))/2;
            acc += dlg[w][i]*rw1[pos*256 + h];
        }
        hreg[m] = acc > 0.f ? acc : expm1f(acc);
    }
    __syncwarp();
    #pragma unroll
    for (int m = 0; m < 8; m++) a[lane + 32*m] = hreg[m];
    __syncwarp();
    for (int o = lane; o < 48; o += 32){
        float acc = rb2[o];
        #pragma unroll 8
        for (int k = 0; k < 256; k++) acc += a[k]*rw2[k*48+o];
        g_rfeat[w][o] = acc;
    }
}

// fused: channel-mix (2oc x 2m register tile, float2) -> 64-tap FIR -> elu -> pool8 -> p1
// grid(63,16), block 512
__global__ void __launch_bounds__(512, 2) k_conv1f(const float* __restrict__ x,
                                                   const float* __restrict__ dw1w,
                                                   const float* __restrict__ c1w){
    extern __shared__ float sm[];
    float* xs = sm;             // 22*322 = 7084 (even stride for float2)
    float* ys = sm + 7084;      // 32*321 = 10272
    float* wT = sm + 17356;     // 22*34 = 748 (transposed weights, even stride)
    float* cws = sm + 18104;    // 16*65 = 1040  (total 19144 floats)
    int b = blockIdx.y, tid = threadIdx.x;
    int u0 = blockIdx.x*32;
    int T0 = u0*8;
    for (int idx = tid; idx < 22*320; idx += 512){
        int ch = idx/320, m = idx - ch*320;
        int t = T0 - 32 + m;
        xs[ch*322+m] = (t >= 0 && t < 16000) ? x[(b*22+ch)*16000 + t] : 0.f;
    }
    for (int idx = tid; idx < 704; idx += 512){
        int oc = idx/22, ch = idx - oc*22;
        wT[ch*34+oc] = dw1w[idx];
    }
    for (int idx = tid; idx < 1024; idx += 512){
        int ic = idx >> 6, k = idx & 63;
        cws[ic*65+k] = c1w[idx];
    }
    __syncthreads();
    // channel mix: 16 oc-pairs x 160 m-pairs
    for (int idx = tid; idx < 2560; idx += 512){
        int ocp = idx/160, mp = idx - ocp*160;
        int oc0 = ocp*2, m = mp*2;
        float a00=0.f, a01=0.f, a10=0.f, a11=0.f;
        #pragma unroll
        for (int ch = 0; ch < 22; ch++){
            float2 xv = *(const float2*)&xs[ch*322+m];
            float2 wv = *(const float2*)&wT[ch*34+oc0];
            a00 += wv.x*xv.x; a01 += wv.x*xv.y;
            a10 += wv.y*xv.x; a11 += wv.y*xv.y;
        }
        ys[oc0*321+m] = a00;   ys[oc0*321+m+1] = a01;
        ys[(oc0+1)*321+m] = a10; ys[(oc0+1)*321+m+1] = a11;
    }
    __syncthreads();
    int oc = tid & 31, grp = tid >> 5;
    const float* yrow = ys + oc*321;
    const float* cw = cws + (oc>>1)*65;
    #pragma unroll 1
    for (int s2 = 0; s2 < 2; s2++){
        int ul = grp*2 + s2;
        int u = u0 + ul;
        int base = 8*ul;
        float acc[8], yr[8];
        #pragma unroll
        for (int s = 0; s < 8; s++){ acc[s]=0.f; yr[s]=yrow[base+s]; }
        #pragma unroll 8
        for (int k = 0; k < 64; k++){
            float w = cw[k];
            #pragma unroll
            for (int s = 0; s < 8; s++) acc[s] += w*yr[s];
            #pragma unroll
            for (int m = 0; m < 7; m++) yr[m] = yr[m+1];
            yr[7] = yrow[base + k + 8];
        }
        if (u < 2000){
            float p = 0.f;
            #pragma unroll
            for (int s = 0; s < 8; s++) p += eluf(BN2F*acc[s]);
            g_p1[(b*32+oc)*2000 + u] = p*0.125f;
        }
    }
}

// dw2 -> pw -> elu -> pool8 -> featA. grid(16,16), block 256. register-blocked pw GEMM.
__global__ void k_c2(const float* __restrict__ dw2w, const float* __restrict__ pww){
    __shared__ float p1s[32*145];
    __shared__ float qs[32*129];
    __shared__ float pwT[32*49];
    __shared__ float dwt[16*33];
    int b = blockIdx.y, tid = threadIdx.x;
    int u0 = blockIdx.x*16;
    int T0 = u0*8;
    for (int idx = tid; idx < 32*144; idx += 256){
        int oc = idx/144, m = idx%144;
        int t = T0 - 8 + m;
        p1s[oc*145+m] = (t >= 0 && t < 2000) ? g_p1[(b*32+oc)*2000 + t] : 0.f;
    }
    for (int idx = tid; idx < 1536; idx += 256){
        int co = idx/32, ci = idx%32;
        pwT[ci*49+co] = pww[idx];
    }
    for (int idx = tid; idx < 512; idx += 256){
        int oc = idx/16, k = idx%16;
        dwt[k*33+oc] = dw2w[idx];
    }
    __syncthreads();
    for (int v = tid; v < 32*128; v += 256){
        int oc = v & 31, t = v >> 5;
        float a = 0.f;
        #pragma unroll
        for (int k = 0; k < 16; k++) a += dwt[k*33+oc]*p1s[oc*145 + t + k];
        qs[oc*129+t] = a*BNF;
    }
    __syncthreads();
    {
        int cog = tid & 15, ul = tid >> 4;
        int u = u0 + ul;
        int co0 = cog*3;
        float acc[3][8];
        #pragma unroll
        for (int j = 0; j < 3; j++)
            #pragma unroll
            for (int s = 0; s < 8; s++) acc[j][s] = 0.f;
        #pragma unroll 4
        for (int ci = 0; ci < 32; ci++){
            float p0 = pwT[ci*49+co0];
            float p1 = pwT[ci*49+co0+1];
            float p2 = pwT[ci*49+co0+2];
            const float* qr = qs + ci*129 + 8*ul;
            #pragma unroll
            for (int s = 0; s < 8; s++){
                float q = qr[s];
                acc[0][s] += p0*q;
                acc[1][s] += p1*q;
                acc[2][s] += p2*q;
            }
        }
        if (u < 250){
            #pragma unroll
            for (int j = 0; j < 3; j++){
                float p = 0.f;
                #pragma unroll
                for (int s = 0; s < 8; s++) p += eluf(BNF*acc[j][s]);
                g_featA[(b*250+u)*48 + co0 + j] = p*0.125f;
            }
        }
    }
}

// temporal conv branch + residual -> featF. grid(4,16), block 256
__global__ void k_tc(const float* __restrict__ tc1w, const float* __restrict__ tc1b,
                     const float* __restrict__ tc2w, const float* __restrict__ tc2b){
    __shared__ float fa[66*48];
    __shared__ float t1s[24*64];
    int b = blockIdx.y, tid = threadIdx.x;
    int u0 = blockIdx.x*64;
    for (int idx = tid; idx < 66*48; idx += 256){
        int r = idx/48, co = idx%48;
        int u = u0 - 1 + r;
        fa[idx] = (u >= 0 && u < 250) ? g_featA[(b*250+u)*48 + co] : 0.f;
    }
    __syncthreads();
    for (int idx = tid; idx < 24*64; idx += 256){
        int g = idx/64, ul = idx%64;
        if (u0 + ul >= 250) continue;
        float a = tc1b[g];
        #pragma unroll
        for (int ci = 0; ci < 2; ci++)
            #pragma unroll
            for (int k = 0; k < 3; k++)
                a += tc1w[(g*2+ci)*3 + k] * fa[(ul+k)*48 + 2*g + ci];
        t1s[g*64+ul] = geluf(BNF*a);
    }
    __syncthreads();
    for (int idx = tid; idx < 48*64; idx += 256){
        int co = idx % 48, ul = idx / 48;
        int u = u0 + ul;
        if (u >= 250) continue;
        float a = tc2b[co];
        #pragma unroll
        for (int g = 0; g < 24; g++) a += tc2w[co*24+g]*t1s[g*64+ul];
        g_featF[(b*250+u)*48 + co] = fa[(ul+1)*48 + co] + a;
    }
}

// fusion proj + pos_enc. grid(251,16), block 48
__global__ void k_fuse(const float* __restrict__ fproj, const float* __restrict__ pe){
    __shared__ float r[48];
    int n = blockIdx.x, b = blockIdx.y, co = threadIdx.x;
    r[co] = (n == 0) ? g_rfeat[b][co] : g_featF[(b*250 + n - 1)*48 + co];
    __syncthreads();
    float a = pe[n*48 + co];
    #pragma unroll 8
    for (int k = 0; k < 48; k++) a += r[k]*fproj[k*48+co];
    g_fused[(b*251+n)*48 + co] = a;
}

// fused LN1 + QKV (halo, 2-row tiled) + banded attention + out proj + residual.
// reads g_fused, writes g_attn. grid(16,16), block 256, dynamic smem.
__global__ void k_attnf(int l, const float* __restrict__ qw, const float* __restrict__ qb,
                        const float* __restrict__ g1, const float* __restrict__ b1,
                        const float* __restrict__ apw, const float* __restrict__ apb){
    extern __shared__ float sm[];
    float* wq  = sm;             // 6912
    float* qs  = sm + 6912;      // 26*144 = 3744
    float* xf  = sm + 10656;     // 26*48 = 1248
    float* hn  = sm + 11904;     // 1248
    float* wp  = sm + 13152;     // 2304
    float* os  = sm + 15456;     // 768
    float* sc  = sm + 16224;     // 1536
    float* qbs = sm + 17760;     // 144
    float* apbs= sm + 17904;     // 48   (total 17952 floats)
    int b = blockIdx.y, tid = threadIdx.x;
    int n0 = blockIdx.x*16;
    const float* wsrc = qw + l*48*144;
    for (int idx = tid; idx < 6912; idx += 256) wq[idx] = wsrc[idx];
    const float* psrc = apw + l*48*48;
    for (int idx = tid; idx < 2304; idx += 256) wp[idx] = psrc[idx];
    if (tid < 144) qbs[tid] = qb[l*144 + tid];
    if (tid < 48) apbs[tid] = apb[l*48 + tid];
    for (int idx = tid; idx < 26*48; idx += 256){
        int r = idx/48, c = idx - r*48;
        int n = n0 - 5 + r;
        xf[idx] = (n >= 0 && n < 251) ? g_fused[(b*251+n)*48 + c] : 0.f;
    }
    __syncthreads();
    {
        int wd = tid >> 5, lane = tid & 31;
        #pragma unroll
        for (int s = 0; s < 4; s++){
            int rl = wd*4 + s;
            if (rl < 26){
                float v0 = xf[rl*48 + lane];
                float v1 = (lane < 16) ? xf[rl*48 + 32 + lane] : 0.f;
                float sum = v0 + v1, sq = v0*v0 + v1*v1;
                #pragma unroll
                for (int o = 16; o; o >>= 1){
                    sum += __shfl_xor_sync(0xffffffffu, sum, o);
                    sq  += __shfl_xor_sync(0xffffffffu, sq, o);
                }
                float m = sum*(1.f/48.f);
                float rinv = rsqrtf(sq*(1.f/48.f) - m*m + 1e-5f);
                hn[rl*48 + lane] = (v0-m)*rinv*g1[l*48+lane] + b1[l*48+lane];
                if (lane < 16) hn[rl*48 + 32 + lane] = (v1-m)*rinv*g1[l*48+32+lane] + b1[l*48+32+lane];
            }
        }
    }
    __syncthreads();
    // qkv for 26 rows: 13 row-pairs x 144 cols
    for (int idx = tid; idx < 13*144; idx += 256){
        int rp = idx/144, col = idx - rp*144;
        int r0 = rp*2;
        float acc0 = qbs[col], acc1 = acc0;
        #pragma unroll 8
        for (int k = 0; k < 48; k++){
            float wv = wq[k*144 + col];
            acc0 += hn[r0*48+k]*wv;
            acc1 += hn[(r0+1)*48+k]*wv;
        }
        qs[r0*144+col] = acc0;
        qs[(r0+1)*144+col] = acc1;
    }
    __syncthreads();
    for (int idx = tid; idx < 1408; idx += 256){
        int tl = idx/88, rem = idx - tl*88, h = rem/11, kk = rem - h*11;
        int n = n0 + tl;
        if (n >= 251) continue;
        int kpos = n - 5 + kk;
        if (kpos < 0 || kpos > 250) continue;
        int rq = tl + 5, rk = tl + kk;
        float s = 0.f;
        #pragma unroll
        for (int d = 0; d < 6; d++) s += qs[rq*144 + h*6 + d]*qs[rk*144 + 48 + h*6 + d];
        sc[(tl*8+h)*12 + kk] = s*ATT_SCALE;
    }
    __syncthreads();
    if (tid < 128){
        int tl = tid >> 3, h = tid & 7;
        int n = n0 + tl;
        if (n < 251){
            int klo = (n - 5 < 0) ? 5 - n : 0;
            int khi = (n + 5 > 250) ? 255 - n : 10;
            float mx = -1e30f;
            for (int kk = klo; kk <= khi; kk++) mx = fmaxf(mx, sc[(tl*8+h)*12+kk]);
            float ss = 0.f;
            for (int kk = klo; kk <= khi; kk++){ float e = __expf(sc[(tl*8+h)*12+kk]-mx); sc[(tl*8+h)*12+kk] = e; ss += e; }
            float inv = 1.f/ss;
            float o[6] = {0,0,0,0,0,0};
            for (int kk = klo; kk <= khi; kk++){
                float p = sc[(tl*8+h)*12+kk]*inv;
                int rk = tl + kk;
                #pragma unroll
                for (int d = 0; d < 6; d++) o[d] += p*qs[rk*144 + 96 + h*6 + d];
            }
            #pragma unroll
            for (int d = 0; d < 6; d++) os[tl*48 + h*6+d] = o[d];
        }
    }
    __syncthreads();
    for (int idx = tid; idx < 768; idx += 256){
        int rl = idx/48, col = idx - rl*48;
        int n = n0 + rl;
        if (n >= 251) continue;
        float acc = apbs[col];
        #pragma unroll 8
        for (int k = 0; k < 48; k++) acc += os[rl*48+k]*wp[k*48 + col];
        g_attn[(b*251+n)*48 + col] = xf[(rl+5)*48 + col] + acc;
    }
}

// LN2 + FFN + residual: reads g_attn, writes g_fused. grid 251, block 384, dyn smem.
// FFN1: 4 rows x 2 cols register tile, float2 weights. FFN2: 2 cols float2.
__global__ void k_ffn(int l, const float* __restrict__ fw1, const float* __restrict__ fb1,
                      const float* __restrict__ fw2, const float* __restrict__ fb2,
                      const float* __restrict__ g2, const float* __restrict__ bb2){
    extern __shared__ float dsm[];
    float* w1s = dsm;                 // 9216
    float* w2s = dsm + 9216;          // 9216
    float* hn  = dsm + 18432;         // 768
    float* h1  = dsm + 19200;         // 3072
    float* xs  = dsm + 22272;         // 768   (total 23040 floats)
    int r0 = blockIdx.x*16;
    int tid = threadIdx.x;
    const float* w1p = fw1 + l*48*192;
    const float* w2p = fw2 + l*192*48;
    for (int idx = tid; idx < 9216; idx += 384){ w1s[idx] = w1p[idx]; w2s[idx] = w2p[idx]; }
    int wd = tid >> 5, lane = tid & 31;
    if (wd < 8){
        #pragma unroll
        for (int s = 0; s < 2; s++){
            int rl = wd*2 + s;
            int row = r0 + rl;
            float v0 = g_attn[row*48 + lane];
            float v1 = (lane < 16) ? g_attn[row*48 + 32 + lane] : 0.f;
            float sum = v0 + v1, sq = v0*v0 + v1*v1;
            #pragma unroll
            for (int o = 16; o; o >>= 1){
                sum += __shfl_xor_sync(0xffffffffu, sum, o);
                sq  += __shfl_xor_sync(0xffffffffu, sq, o);
            }
            float m = sum*(1.f/48.f);
            float rinv = rsqrtf(sq*(1.f/48.f) - m*m + 1e-5f);
            xs[rl*48 + lane] = v0;
            hn[rl*48 + lane] = (v0-m)*rinv*g2[l*48+lane] + bb2[l*48+lane];
            if (lane < 16){
                xs[rl*48 + 32 + lane] = v1;
                hn[rl*48 + 32 + lane] = (v1-m)*rinv*g2[l*48+32+lane] + bb2[l*48+32+lane];
            }
        }
    }
    __syncthreads();
    // FFN1: 4 rowgroups(4 rows) x 96 colpairs
    {
        int g = tid/96, cp = tid - (tid/96)*96;
        int col0 = cp*2;
        float2 bv = make_float2(fb1[l*192 + col0], fb1[l*192 + col0 + 1]);
        float2 acc[4];
        #pragma unroll
        for (int r = 0; r < 4; r++) acc[r] = bv;
        const float2* w1v = (const float2*)w1s;
        #pragma unroll 4
        for (int k = 0; k < 48; k++){
            float2 wv = w1v[k*96 + cp];
            #pragma unroll
            for (int r = 0; r < 4; r++){
                float hv = hn[(g*4+r)*48 + k];
                acc[r].x += hv*wv.x;
                acc[r].y += hv*wv.y;
            }
        }
        #pragma unroll
        for (int r = 0; r < 4; r++){
            h1[(g*4+r)*192 + col0]     = geluf(acc[r].x);
            h1[(g*4+r)*192 + col0 + 1] = geluf(acc[r].y);
        }
    }
    __syncthreads();
    // FFN2: 16 rows x 24 colpairs
    {
        int row = tid/24, cp = tid - (tid/24)*24;
        int col0 = cp*2;
        float2 acc = make_float2(fb2[l*48 + col0], fb2[l*48 + col0 + 1]);
        const float2* w2v = (const float2*)w2s;
        #pragma unroll 4
        for (int k = 0; k < 192; k++){
            float2 wv = w2v[k*24 + cp];
            float hv = h1[row*192 + k];
            acc.x += hv*wv.x;
            acc.y += hv*wv.y;
        }
        int n = r0 + row;
        g_fused[n*48 + col0]     = xs[row*48 + col0]     + acc.x;
        g_fused[n*48 + col0 + 1] = xs[row*48 + col0 + 1] + acc.y;
    }
}

// mean over tokens + LN + classifier. grid 16, block 64
__global__ void k_head(const float* __restrict__ cg, const float* __restrict__ cb,
                       const float* __restrict__ cw, const float* __restrict__ cbias,
                       float* __restrict__ out){
    __shared__ float gm[48];
    int b = blockIdx.x, tid = threadIdx.x;
    if (tid < 48){
        float s = 0.f;
        for (int n = 0; n < 251; n++) s += g_fused[(b*251+n)*48 + tid];
        gm[tid] = s*(1.f/251.f);
    }
    __syncthreads();
    if (tid < 4){
        float m = 0.f;
        #pragma unroll 8
        for (int k = 0; k < 48; k++) m += gm[k];
        m *= (1.f/48.f);
        float v = 0.f;
        #pragma unroll 8
        for (int k = 0; k < 48; k++){ float d = gm[k]-m; v += d*d; }
        float rinv = rsqrtf(v*(1.f/48.f) + 1e-5f);
        float a = cbias[tid];
        #pragma unroll 8
        for (int k = 0; k < 48; k++){
            float gn = (gm[k]-m)*rinv*cg[k] + cb[k];
            a += gn*cw[k*4 + tid];
        }
        out[b*4 + tid] = a;
    }
}

#define CONV1F_SMEM (19144*4)
#define ATTNF_SMEM  (17952*4)
#define FFN_SMEM    (23040*4)

extern "C" void kernel_launch(void* const* d_in, const int* in_sizes, int n_in,
                              void* d_out, int out_size) {
    const float* x      = (const float*)d_in[0];
    const float* rw1    = (const float*)d_in[1];
    const float* rb1    = (const float*)d_in[2];
    const float* rw2    = (const float*)d_in[3];
    const float* rb2    = (const float*)d_in[4];
    const float* c1w    = (const float*)d_in[5];
    const float* dw1w   = (const float*)d_in[6];
    const float* dw2w   = (const float*)d_in[7];
    const float* pww    = (const float*)d_in[8];
    const float* tc1w   = (const float*)d_in[9];
    const float* tc1b   = (const float*)d_in[10];
    const float* tc2w   = (const float*)d_in[11];
    const float* tc2b   = (const float*)d_in[12];
    const float* fproj  = (const float*)d_in[13];
    const float* pe     = (const float*)d_in[14];
    const float* ln1g   = (const float*)d_in[15];
    const float* ln1b   = (const float*)d_in[16];
    const float* qkvw   = (const float*)d_in[17];
    const float* qkvb   = (const float*)d_in[18];
    const float* apw    = (const float*)d_in[19];
    const float* apb    = (const float*)d_in[20];
    const float* ln2g   = (const float*)d_in[21];
    const float* ln2b   = (const float*)d_in[22];
    const float* fw1    = (const float*)d_in[23];
    const float* fb1    = (const float*)d_in[24];
    const float* fw2    = (const float*)d_in[25];
    const float* fb2    = (const float*)d_in[26];
    const float* clsg   = (const float*)d_in[27];
    const float* clsb   = (const float*)d_in[28];
    const float* clsw   = (const float*)d_in[29];
    const float* clsbias= (const float*)d_in[30];
    float* out = (float*)d_out;

    static int attr_set = 0;
    if (!attr_set){
        cudaFuncSetAttribute(k_conv1f, cudaFuncAttributeMaxDynamicSharedMemorySize, CONV1F_SMEM);
        cudaFuncSetAttribute(k_attnf,  cudaFuncAttributeMaxDynamicSharedMemorySize, ATTNF_SMEM);
        cudaFuncSetAttribute(k_ffn,    cudaFuncAttributeMaxDynamicSharedMemorySize, FFN_SMEM);
        attr_set = 1;
    }

    k_covp<<<dim3(8,16), 288>>>(x);
    k_spd<<<1, 512>>>(rw1, rb1, rw2, rb2);
    k_conv1f<<<dim3(63,16), 512, CONV1F_SMEM>>>(x, dw1w, c1w);
    k_c2<<<dim3(16,16), 256>>>(dw2w, pww);
    k_tc<<<dim3(4,16), 256>>>(tc1w, tc1b, tc2w, tc2b);
    k_fuse<<<dim3(251,16), 48>>>(fproj, pe);
    for (int l = 0; l < 4; l++){
        k_attnf<<<dim3(16,16), 256, ATTNF_SMEM>>>(l, qkvw, qkvb, ln1g, ln1b, apw, apb);
        k_ffn<<<251, 384, FFN_SMEM>>>(l, fw1, fb1, fw2, fb2, ln2g, ln2b);
    }
    k_head<<<16, 64>>>(clsg, clsb, clsw, clsbias, out);
}

// round 15
// speedup vs baseline: 1.4245x; 1.2300x over previous
#include <cuda_runtime.h>
#include <cuda_bf16.h>
#include <math.h>

#define BNF 0.9999950000374997f
#define BN2F 0.9999900000999990f
#define ATT_SCALE 0.40824829046386301637f

// ---- scratch ----
__device__ float g_covp[16][16][288];
__device__ float g_rfeat[16][48];
__device__ float g_p1[16*32*2000];
__device__ float g_featA[16*250*48];
__device__ float g_featF[16*250*48];
__device__ float g_fused[16*251*48];
__device__ float g_attn[16*251*48];

__device__ __forceinline__ float eluf(float x){ return x > 0.f ? x : (__expf(x) - 1.f); }
__device__ __forceinline__ float geluf(float x){ return 0.5f*x*(1.f+erff(x*0.70710678118654752f)); }

// covariance partial sums: grid(16 chunks,16 b), block 288, 4 tiles of 250 each
__global__ void k_covp(const float* __restrict__ x){
    __shared__ float xs[22*253];
    int b = blockIdx.y, ch = blockIdx.x, tid = threadIdx.x;
    int i=0,j=0;
    if (tid < 253){ int p=tid; while (p >= 22-i){ p -= 22-i; i++; } j = i+p; }
    int c = tid - 253;
    float acc = 0.f;
    for (int tile = 0; tile < 4; tile++){
        int t0 = ch*1000 + tile*250;
        for (int idx = tid; idx < 22*250; idx += 288){
            int cc = idx/250, t = idx%250;
            xs[cc*253+t] = x[(b*22+cc)*16000 + t0 + t];
        }
        __syncthreads();
        if (tid < 253){
            const float* xi = xs + i*253;
            const float* xj = xs + j*253;
            #pragma unroll 5
            for (int t = 0; t < 250; t++) acc += xi[t]*xj[t];
        } else if (tid < 275){
            const float* xc = xs + c*253;
            #pragma unroll 5
            for (int t = 0; t < 250; t++) acc += xc[t];
        }
        __syncthreads();
    }
    if (tid < 275) g_covp[b][ch][tid] = acc;
}

// merged covred + ridge + cholesky + dlog + riem MLP. 1 block, 512 threads (warp = batch)
__global__ void k_spd(const float* __restrict__ rw1, const float* __restrict__ rb1,
                      const float* __restrict__ rw2, const float* __restrict__ rb2){
    __shared__ float A[16*484];
    __shared__ float chs[16][22];
    __shared__ float dlg[16][22];
    __shared__ float trs[16];
    __shared__ float trm;
    int tid = threadIdx.x, w = tid >> 5, lane = tid & 31;
    float* a = A + w*484;
    if (lane < 22){
        float s = 0.f;
        #pragma unroll
        for (int c = 0; c < 16; c++) s += g_covp[w][c][253+lane];
        chs[w][lane] = s;
    }
    __syncwarp();
    for (int p = lane; p < 253; p += 32){
        int i=0,q=p; while (q >= 22-i){ q -= 22-i; i++; } int j = i+q;
        float s = 0.f;
        #pragma unroll
        for (int c = 0; c < 16; c++) s += g_covp[w][c][p];
        float cov = (s - chs[w][i]*chs[w][j]*(1.f/16000.f)) * (1.f/15999.f);
        if (i == j) cov += 1e-5f;
        a[i*22+j] = cov;
        a[j*22+i] = cov;
    }
    __syncwarp();
    if (lane == 0){ float tr=0.f; for (int k=0;k<22;k++) tr += a[k*22+k]; trs[w]=tr; }
    __syncthreads();
    if (tid == 0){ float s=0.f; for (int b=0;b<16;b++) s += trs[b]; trm = s*(0.001f/16.f); }
    __syncthreads();
    if (lane < 22) a[lane*22+lane] += trm;
    __syncwarp();
    for (int jj = 0; jj < 22; jj++){
        float dj = 0.f;
        if (lane == jj){ dj = sqrtf(a[jj*22+jj]); a[jj*22+jj] = dj; }
        dj = __shfl_sync(0xffffffffu, dj, jj);
        if (lane > jj && lane < 22) a[lane*22+jj] /= dj;
        __syncwarp();
        if (lane > jj && lane < 22){
            float lij = a[lane*22+jj];
            for (int k = jj+1; k <= lane; k++) a[lane*22+k] -= lij * a[k*22+jj];
        }
        __syncwarp();
    }
    if (lane < 22){
        float d = a[lane*22+lane];
        dlg[w][lane] = d * logf(fmaxf(d, 1e-10f));
    }
    __syncwarp();
    float hreg[8];
    #pragma unroll
    for (int m = 0; m < 8; m++){
        int h = lane + 32*m;
        float acc = rb1[h];
        #pragma unroll
        for (int i = 0; i < 22; i++){
            int pos = i*22 - (i*(i-1))/2;
            acc += dlg[w][i]*rw1[pos*256 + h];
        }
        hreg[m] = acc > 0.f ? acc : expm1f(acc);
    }
    __syncwarp();
    #pragma unroll
    for (int m = 0; m < 8; m++) a[lane + 32*m] = hreg[m];
    __syncwarp();
    for (int o = lane; o < 48; o += 32){
        float acc = rb2[o];
        #pragma unroll 8
        for (int k = 0; k < 256; k++) acc += a[k]*rw2[k*48+o];
        g_rfeat[w][o] = acc;
    }
}

// fused: channel-mix (2oc x 2m register tile, float2) -> 64-tap FIR -> elu -> pool8 -> p1
// grid(63,16), block 512
__global__ void __launch_bounds__(512, 2) k_conv1f(const float* __restrict__ x,
                                                   const float* __restrict__ dw1w,
                                                   const float* __restrict__ c1w){
    extern __shared__ float sm[];
    float* xs = sm;             // 22*322 = 7084
    float* ys = sm + 7084;      // 32*321 = 10272
    float* wT = sm + 17356;     // 22*34 = 748
    float* cws = sm + 18104;    // 16*65 = 1040  (total 19144 floats)
    int b = blockIdx.y, tid = threadIdx.x;
    int u0 = blockIdx.x*32;
    int T0 = u0*8;
    for (int idx = tid; idx < 22*320; idx += 512){
        int ch = idx/320, m = idx - ch*320;
        int t = T0 - 32 + m;
        xs[ch*322+m] = (t >= 0 && t < 16000) ? x[(b*22+ch)*16000 + t] : 0.f;
    }
    for (int idx = tid; idx < 704; idx += 512){
        int oc = idx/22, ch = idx - oc*22;
        wT[ch*34+oc] = dw1w[idx];
    }
    for (int idx = tid; idx < 1024; idx += 512){
        int ic = idx >> 6, k = idx & 63;
        cws[ic*65+k] = c1w[idx];
    }
    __syncthreads();
    for (int idx = tid; idx < 2560; idx += 512){
        int ocp = idx/160, mp = idx - ocp*160;
        int oc0 = ocp*2, m = mp*2;
        float a00=0.f, a01=0.f, a10=0.f, a11=0.f;
        #pragma unroll
        for (int ch = 0; ch < 22; ch++){
            float2 xv = *(const float2*)&xs[ch*322+m];
            float2 wv = *(const float2*)&wT[ch*34+oc0];
            a00 += wv.x*xv.x; a01 += wv.x*xv.y;
            a10 += wv.y*xv.x; a11 += wv.y*xv.y;
        }
        ys[oc0*321+m] = a00;   ys[oc0*321+m+1] = a01;
        ys[(oc0+1)*321+m] = a10; ys[(oc0+1)*321+m+1] = a11;
    }
    __syncthreads();
    int oc = tid & 31, grp = tid >> 5;
    const float* yrow = ys + oc*321;
    const float* cw = cws + (oc>>1)*65;
    #pragma unroll 1
    for (int s2 = 0; s2 < 2; s2++){
        int ul = grp*2 + s2;
        int u = u0 + ul;
        int base = 8*ul;
        float acc[8], yr[8];
        #pragma unroll
        for (int s = 0; s < 8; s++){ acc[s]=0.f; yr[s]=yrow[base+s]; }
        #pragma unroll 8
        for (int k = 0; k < 64; k++){
            float w = cw[k];
            #pragma unroll
            for (int s = 0; s < 8; s++) acc[s] += w*yr[s];
            #pragma unroll
            for (int m = 0; m < 7; m++) yr[m] = yr[m+1];
            yr[7] = yrow[base + k + 8];
        }
        if (u < 2000){
            float p = 0.f;
            #pragma unroll
            for (int s = 0; s < 8; s++) p += eluf(BN2F*acc[s]);
            g_p1[(b*32+oc)*2000 + u] = p*0.125f;
        }
    }
}

// dw2 -> pw -> elu -> pool8 -> featA. grid(32,16), block 128, 8 u per block.
__global__ void k_c2(const float* __restrict__ dw2w, const float* __restrict__ pww){
    __shared__ float p1s[32*81];
    __shared__ float qs[32*65];
    __shared__ float pwT[32*49];
    __shared__ float dwt[16*33];
    int b = blockIdx.y, tid = threadIdx.x;
    int u0 = blockIdx.x*8;
    int T0 = u0*8;
    for (int idx = tid; idx < 32*80; idx += 128){
        int oc = idx/80, m = idx - (idx/80)*80;
        int t = T0 - 8 + m;
        p1s[oc*81+m] = (t >= 0 && t < 2000) ? g_p1[(b*32+oc)*2000 + t] : 0.f;
    }
    for (int idx = tid; idx < 1536; idx += 128){
        int co = idx/32, ci = idx%32;
        pwT[ci*49+co] = pww[idx];
    }
    for (int idx = tid; idx < 512; idx += 128){
        int oc = idx/16, k = idx%16;
        dwt[k*33+oc] = dw2w[idx];
    }
    __syncthreads();
    for (int v = tid; v < 2048; v += 128){
        int oc = v & 31, t = v >> 5;
        float a = 0.f;
        #pragma unroll
        for (int k = 0; k < 16; k++) a += dwt[k*33+oc]*p1s[oc*81 + t + k];
        qs[oc*65+t] = a*BNF;
    }
    __syncthreads();
    {
        int cog = tid & 15, ul = tid >> 4;
        int u = u0 + ul;
        int co0 = cog*3;
        float acc[3][8];
        #pragma unroll
        for (int j = 0; j < 3; j++)
            #pragma unroll
            for (int s = 0; s < 8; s++) acc[j][s] = 0.f;
        #pragma unroll 4
        for (int ci = 0; ci < 32; ci++){
            float p0 = pwT[ci*49+co0];
            float p1 = pwT[ci*49+co0+1];
            float p2 = pwT[ci*49+co0+2];
            const float* qr = qs + ci*65 + 8*ul;
            #pragma unroll
            for (int s = 0; s < 8; s++){
                float q = qr[s];
                acc[0][s] += p0*q;
                acc[1][s] += p1*q;
                acc[2][s] += p2*q;
            }
        }
        if (u < 250){
            #pragma unroll
            for (int j = 0; j < 3; j++){
                float p = 0.f;
                #pragma unroll
                for (int s = 0; s < 8; s++) p += eluf(BNF*acc[j][s]);
                g_featA[(b*250+u)*48 + co0 + j] = p*0.125f;
            }
        }
    }
}

// temporal conv branch + residual -> featF. grid(4,16), block 256
__global__ void k_tc(const float* __restrict__ tc1w, const float* __restrict__ tc1b,
                     const float* __restrict__ tc2w, const float* __restrict__ tc2b){
    __shared__ float fa[66*48];
    __shared__ float t1s[24*64];
    int b = blockIdx.y, tid = threadIdx.x;
    int u0 = blockIdx.x*64;
    for (int idx = tid; idx < 66*48; idx += 256){
        int r = idx/48, co = idx%48;
        int u = u0 - 1 + r;
        fa[idx] = (u >= 0 && u < 250) ? g_featA[(b*250+u)*48 + co] : 0.f;
    }
    __syncthreads();
    for (int idx = tid; idx < 24*64; idx += 256){
        int g = idx/64, ul = idx%64;
        if (u0 + ul >= 250) continue;
        float a = tc1b[g];
        #pragma unroll
        for (int ci = 0; ci < 2; ci++)
            #pragma unroll
            for (int k = 0; k < 3; k++)
                a += tc1w[(g*2+ci)*3 + k] * fa[(ul+k)*48 + 2*g + ci];
        t1s[g*64+ul] = geluf(BNF*a);
    }
    __syncthreads();
    for (int idx = tid; idx < 48*64; idx += 256){
        int co = idx % 48, ul = idx / 48;
        int u = u0 + ul;
        if (u >= 250) continue;
        float a = tc2b[co];
        #pragma unroll
        for (int g = 0; g < 24; g++) a += tc2w[co*24+g]*t1s[g*64+ul];
        g_featF[(b*250+u)*48 + co] = fa[(ul+1)*48 + co] + a;
    }
}

// fusion proj + pos_enc. grid(251,16), block 48
__global__ void k_fuse(const float* __restrict__ fproj, const float* __restrict__ pe){
    __shared__ float r[48];
    int n = blockIdx.x, b = blockIdx.y, co = threadIdx.x;
    r[co] = (n == 0) ? g_rfeat[b][co] : g_featF[(b*250 + n - 1)*48 + co];
    __syncthreads();
    float a = pe[n*48 + co];
    #pragma unroll 8
    for (int k = 0; k < 48; k++) a += r[k]*fproj[k*48+co];
    g_fused[(b*251+n)*48 + co] = a;
}

// fused LN1 + QKV (halo, 2-row tiled) + banded attention + out proj + residual.
__global__ void k_attnf(int l, const float* __restrict__ qw, const float* __restrict__ qb,
                        const float* __restrict__ g1, const float* __restrict__ b1,
                        const float* __restrict__ apw, const float* __restrict__ apb){
    extern __shared__ float sm[];
    float* wq  = sm;             // 6912
    float* qs  = sm + 6912;      // 3744
    float* xf  = sm + 10656;     // 1248
    float* hn  = sm + 11904;     // 1248
    float* wp  = sm + 13152;     // 2304
    float* os  = sm + 15456;     // 768
    float* sc  = sm + 16224;     // 1536
    float* qbs = sm + 17760;     // 144
    float* apbs= sm + 17904;     // 48   (total 17952 floats)
    int b = blockIdx.y, tid = threadIdx.x;
    int n0 = blockIdx.x*16;
    const float* wsrc = qw + l*48*144;
    for (int idx = tid; idx < 6912; idx += 256) wq[idx] = wsrc[idx];
    const float* psrc = apw + l*48*48;
    for (int idx = tid; idx < 2304; idx += 256) wp[idx] = psrc[idx];
    if (tid < 144) qbs[tid] = qb[l*144 + tid];
    if (tid < 48) apbs[tid] = apb[l*48 + tid];
    for (int idx = tid; idx < 26*48; idx += 256){
        int r = idx/48, c = idx - r*48;
        int n = n0 - 5 + r;
        xf[idx] = (n >= 0 && n < 251) ? g_fused[(b*251+n)*48 + c] : 0.f;
    }
    __syncthreads();
    {
        int wd = tid >> 5, lane = tid & 31;
        #pragma unroll
        for (int s = 0; s < 4; s++){
            int rl = wd*4 + s;
            if (rl < 26){
                float v0 = xf[rl*48 + lane];
                float v1 = (lane < 16) ? xf[rl*48 + 32 + lane] : 0.f;
                float sum = v0 + v1, sq = v0*v0 + v1*v1;
                #pragma unroll
                for (int o = 16; o; o >>= 1){
                    sum += __shfl_xor_sync(0xffffffffu, sum, o);
                    sq  += __shfl_xor_sync(0xffffffffu, sq, o);
                }
                float m = sum*(1.f/48.f);
                float rinv = rsqrtf(sq*(1.f/48.f) - m*m + 1e-5f);
                hn[rl*48 + lane] = (v0-m)*rinv*g1[l*48+lane] + b1[l*48+lane];
                if (lane < 16) hn[rl*48 + 32 + lane] = (v1-m)*rinv*g1[l*48+32+lane] + b1[l*48+32+lane];
            }
        }
    }
    __syncthreads();
    for (int idx = tid; idx < 13*144; idx += 256){
        int rp = idx/144, col = idx - rp*144;
        int r0 = rp*2;
        float acc0 = qbs[col], acc1 = acc0;
        #pragma unroll 8
        for (int k = 0; k < 48; k++){
            float wv = wq[k*144 + col];
            acc0 += hn[r0*48+k]*wv;
            acc1 += hn[(r0+1)*48+k]*wv;
        }
        qs[r0*144+col] = acc0;
        qs[(r0+1)*144+col] = acc1;
    }
    __syncthreads();
    for (int idx = tid; idx < 1408; idx += 256){
        int tl = idx/88, rem = idx - tl*88, h = rem/11, kk = rem - h*11;
        int n = n0 + tl;
        if (n >= 251) continue;
        int kpos = n - 5 + kk;
        if (kpos < 0 || kpos > 250) continue;
        int rq = tl + 5, rk = tl + kk;
        float s = 0.f;
        #pragma unroll
        for (int d = 0; d < 6; d++) s += qs[rq*144 + h*6 + d]*qs[rk*144 + 48 + h*6 + d];
        sc[(tl*8+h)*12 + kk] = s*ATT_SCALE;
    }
    __syncthreads();
    if (tid < 128){
        int tl = tid >> 3, h = tid & 7;
        int n = n0 + tl;
        if (n < 251){
            int klo = (n - 5 < 0) ? 5 - n : 0;
            int khi = (n + 5 > 250) ? 255 - n : 10;
            float mx = -1e30f;
            for (int kk = klo; kk <= khi; kk++) mx = fmaxf(mx, sc[(tl*8+h)*12+kk]);
            float ss = 0.f;
            for (int kk = klo; kk <= khi; kk++){ float e = __expf(sc[(tl*8+h)*12+kk]-mx); sc[(tl*8+h)*12+kk] = e; ss += e; }
            float inv = 1.f/ss;
            float o[6] = {0,0,0,0,0,0};
            for (int kk = klo; kk <= khi; kk++){
                float p = sc[(tl*8+h)*12+kk]*inv;
                int rk = tl + kk;
                #pragma unroll
                for (int d = 0; d < 6; d++) o[d] += p*qs[rk*144 + 96 + h*6 + d];
            }
            #pragma unroll
            for (int d = 0; d < 6; d++) os[tl*48 + h*6+d] = o[d];
        }
    }
    __syncthreads();
    for (int idx = tid; idx < 768; idx += 256){
        int rl = idx/48, col = idx - rl*48;
        int n = n0 + rl;
        if (n >= 251) continue;
        float acc = apbs[col];
        #pragma unroll 8
        for (int k = 0; k < 48; k++) acc += os[rl*48+k]*wp[k*48 + col];
        g_attn[(b*251+n)*48 + col] = xf[(rl+5)*48 + col] + acc;
    }
}

// LN2 + FFN + residual: reads g_attn, writes g_fused. grid 251, block 384, dyn smem.
__global__ void k_ffn(int l, const float* __restrict__ fw1, const float* __restrict__ fb1,
                      const float* __restrict__ fw2, const float* __restrict__ fb2,
                      const float* __restrict__ g2, const float* __restrict__ bb2){
    extern __shared__ float dsm[];
    float* w1s = dsm;                 // 9216
    float* w2s = dsm + 9216;          // 9216
    float* hn  = dsm + 18432;         // 768
    float* h1  = dsm + 19200;         // 3072
    float* xs  = dsm + 22272;         // 768   (total 23040 floats)
    int r0 = blockIdx.x*16;
    int tid = threadIdx.x;
    const float* w1p = fw1 + l*48*192;
    const float* w2p = fw2 + l*192*48;
    for (int idx = tid; idx < 9216; idx += 384){ w1s[idx] = w1p[idx]; w2s[idx] = w2p[idx]; }
    int wd = tid >> 5, lane = tid & 31;
    if (wd < 8){
        #pragma unroll
        for (int s = 0; s < 2; s++){
            int rl = wd*2 + s;
            int row = r0 + rl;
            float v0 = g_attn[row*48 + lane];
            float v1 = (lane < 16) ? g_attn[row*48 + 32 + lane] : 0.f;
            float sum = v0 + v1, sq = v0*v0 + v1*v1;
            #pragma unroll
            for (int o = 16; o; o >>= 1){
                sum += __shfl_xor_sync(0xffffffffu, sum, o);
                sq  += __shfl_xor_sync(0xffffffffu, sq, o);
            }
            float m = sum*(1.f/48.f);
            float rinv = rsqrtf(sq*(1.f/48.f) - m*m + 1e-5f);
            xs[rl*48 + lane] = v0;
            hn[rl*48 + lane] = (v0-m)*rinv*g2[l*48+lane] + bb2[l*48+lane];
            if (lane < 16){
                xs[rl*48 + 32 + lane] = v1;
                hn[rl*48 + 32 + lane] = (v1-m)*rinv*g2[l*48+32+lane] + bb2[l*48+32+lane];
            }
        }
    }
    __syncthreads();
    {
        int g = tid/96, cp = tid - (tid/96)*96;
        int col0 = cp*2;
        float2 bv = make_float2(fb1[l*192 + col0], fb1[l*192 + col0 + 1]);
        float2 acc[4];
        #pragma unroll
        for (int r = 0; r < 4; r++) acc[r] = bv;
        const float2* w1v = (const float2*)w1s;
        #pragma unroll 4
        for (int k = 0; k < 48; k++){
            float2 wv = w1v[k*96 + cp];
            #pragma unroll
            for (int r = 0; r < 4; r++){
                float hv = hn[(g*4+r)*48 + k];
                acc[r].x += hv*wv.x;
                acc[r].y += hv*wv.y;
            }
        }
        #pragma unroll
        for (int r = 0; r < 4; r++){
            h1[(g*4+r)*192 + col0]     = geluf(acc[r].x);
            h1[(g*4+r)*192 + col0 + 1] = geluf(acc[r].y);
        }
    }
    __syncthreads();
    {
        int row = tid/24, cp = tid - (tid/24)*24;
        int col0 = cp*2;
        float2 acc = make_float2(fb2[l*48 + col0], fb2[l*48 + col0 + 1]);
        const float2* w2v = (const float2*)w2s;
        #pragma unroll 4
        for (int k = 0; k < 192; k++){
            float2 wv = w2v[k*24 + cp];
            float hv = h1[row*192 + k];
            acc.x += hv*wv.x;
            acc.y += hv*wv.y;
        }
        int n = r0 + row;
        g_fused[n*48 + col0]     = xs[row*48 + col0]     + acc.x;
        g_fused[n*48 + col0 + 1] = xs[row*48 + col0 + 1] + acc.y;
    }
}

// mean over tokens + LN + classifier. grid 16, block 64
__global__ void k_head(const float* __restrict__ cg, const float* __restrict__ cb,
                       const float* __restrict__ cw, const float* __restrict__ cbias,
                       float* __restrict__ out){
    __shared__ float gm[48];
    int b = blockIdx.x, tid = threadIdx.x;
    if (tid < 48){
        float s = 0.f;
        for (int n = 0; n < 251; n++) s += g_fused[(b*251+n)*48 + tid];
        gm[tid] = s*(1.f/251.f);
    }
    __syncthreads();
    if (tid < 4){
        float m = 0.f;
        #pragma unroll 8
        for (int k = 0; k < 48; k++) m += gm[k];
        m *= (1.f/48.f);
        float v = 0.f;
        #pragma unroll 8
        for (int k = 0; k < 48; k++){ float d = gm[k]-m; v += d*d; }
        float rinv = rsqrtf(v*(1.f/48.f) + 1e-5f);
        float a = cbias[tid];
        #pragma unroll 8
        for (int k = 0; k < 48; k++){
            float gn = (gm[k]-m)*rinv*cg[k] + cb[k];
            a += gn*cw[k*4 + tid];
        }
        out[b*4 + tid] = a;
    }
}

#define CONV1F_SMEM (19144*4)
#define ATTNF_SMEM  (17952*4)
#define FFN_SMEM    (23040*4)

extern "C" void kernel_launch(void* const* d_in, const int* in_sizes, int n_in,
                              void* d_out, int out_size) {
    const float* x      = (const float*)d_in[0];
    const float* rw1    = (const float*)d_in[1];
    const float* rb1    = (const float*)d_in[2];
    const float* rw2    = (const float*)d_in[3];
    const float* rb2    = (const float*)d_in[4];
    const float* c1w    = (const float*)d_in[5];
    const float* dw1w   = (const float*)d_in[6];
    const float* dw2w   = (const float*)d_in[7];
    const float* pww    = (const float*)d_in[8];
    const float* tc1w   = (const float*)d_in[9];
    const float* tc1b   = (const float*)d_in[10];
    const float* tc2w   = (const float*)d_in[11];
    const float* tc2b   = (const float*)d_in[12];
    const float* fproj  = (const float*)d_in[13];
    const float* pe     = (const float*)d_in[14];
    const float* ln1g   = (const float*)d_in[15];
    const float* ln1b   = (const float*)d_in[16];
    const float* qkvw   = (const float*)d_in[17];
    const float* qkvb   = (const float*)d_in[18];
    const float* apw    = (const float*)d_in[19];
    const float* apb    = (const float*)d_in[20];
    const float* ln2g   = (const float*)d_in[21];
    const float* ln2b   = (const float*)d_in[22];
    const float* fw1    = (const float*)d_in[23];
    const float* fb1    = (const float*)d_in[24];
    const float* fw2    = (const float*)d_in[25];
    const float* fb2    = (const float*)d_in[26];
    const float* clsg   = (const float*)d_in[27];
    const float* clsb   = (const float*)d_in[28];
    const float* clsw   = (const float*)d_in[29];
    const float* clsbias= (const float*)d_in[30];
    float* out = (float*)d_out;

    static cudaStream_t s2 = nullptr;
    static cudaEvent_t eFork = nullptr, eJoin = nullptr;
    static int attr_set = 0;
    if (!attr_set){
        cudaFuncSetAttribute(k_conv1f, cudaFuncAttributeMaxDynamicSharedMemorySize, CONV1F_SMEM);
        cudaFuncSetAttribute(k_attnf,  cudaFuncAttributeMaxDynamicSharedMemorySize, ATTNF_SMEM);
        cudaFuncSetAttribute(k_ffn,    cudaFuncAttributeMaxDynamicSharedMemorySize, FFN_SMEM);
        cudaStreamCreateWithFlags(&s2, cudaStreamNonBlocking);
        cudaEventCreateWithFlags(&eFork, cudaEventDisableTiming);
        cudaEventCreateWithFlags(&eJoin, cudaEventDisableTiming);
        attr_set = 1;
    }

    // fork: SPD chain on s2, conv chain on default stream
    cudaEventRecord(eFork, 0);
    cudaStreamWaitEvent(s2, eFork, 0);
    k_covp<<<dim3(16,16), 288, 0, s2>>>(x);
    k_spd<<<1, 512, 0, s2>>>(rw1, rb1, rw2, rb2);
    cudaEventRecord(eJoin, s2);

    k_conv1f<<<dim3(63,16), 512, CONV1F_SMEM>>>(x, dw1w, c1w);
    k_c2<<<dim3(32,16), 128>>>(dw2w, pww);
    k_tc<<<dim3(4,16), 256>>>(tc1w, tc1b, tc2w, tc2b);

    // join before fusion
    cudaStreamWaitEvent(0, eJoin, 0);
    k_fuse<<<dim3(251,16), 48>>>(fproj, pe);
    for (int l = 0; l < 4; l++){
        k_attnf<<<dim3(16,16), 256, ATTNF_SMEM>>>(l, qkvw, qkvb, ln1g, ln1b, apw, apb);
        k_ffn<<<251, 384, FFN_SMEM>>>(l, fw1, fb1, fw2, fb2, ln2g, ln2b);
    }
    k_head<<<16, 64>>>(clsg, clsb, clsw, clsbias, out);
}

// round 16
// speedup vs baseline: 1.4576x; 1.0232x over previous
#include <cuda_runtime.h>
#include <cuda_bf16.h>
#include <math.h>

#define BNF 0.9999950000374997f
#define BN2F 0.9999900000999990f
#define ATT_SCALE 0.40824829046386301637f

// ---- scratch ----
__device__ float g_covp[16][16][288];
__device__ float g_rfeat[16][48];
__device__ float g_p1[16*32*2000];
__device__ float g_featA[16*250*48];
__device__ float g_featF[16*250*48];
__device__ float g_fused[16*251*48];
__device__ float g_attn[16*251*48];

__device__ __forceinline__ float eluf(float x){ return x > 0.f ? x : (__expf(x) - 1.f); }
__device__ __forceinline__ float geluf(float x){ return 0.5f*x*(1.f+erff(x*0.70710678118654752f)); }

// covariance partial sums: grid(16 chunks,16 b), block 288, 4 tiles of 250 each
__global__ void k_covp(const float* __restrict__ x){
    __shared__ float xs[22*253];
    int b = blockIdx.y, ch = blockIdx.x, tid = threadIdx.x;
    int i=0,j=0;
    if (tid < 253){ int p=tid; while (p >= 22-i){ p -= 22-i; i++; } j = i+p; }
    int c = tid - 253;
    float acc = 0.f;
    for (int tile = 0; tile < 4; tile++){
        int t0 = ch*1000 + tile*250;
        for (int idx = tid; idx < 22*250; idx += 288){
            int cc = idx/250, t = idx%250;
            xs[cc*253+t] = x[(b*22+cc)*16000 + t0 + t];
        }
        __syncthreads();
        if (tid < 253){
            const float* xi = xs + i*253;
            const float* xj = xs + j*253;
            #pragma unroll 5
            for (int t = 0; t < 250; t++) acc += xi[t]*xj[t];
        } else if (tid < 275){
            const float* xc = xs + c*253;
            #pragma unroll 5
            for (int t = 0; t < 250; t++) acc += xc[t];
        }
        __syncthreads();
    }
    if (tid < 275) g_covp[b][ch][tid] = acc;
}

// merged covred + ridge + cholesky + dlog + riem MLP. 1 block, 512 threads (warp = batch)
__global__ void k_spd(const float* __restrict__ rw1, const float* __restrict__ rb1,
                      const float* __restrict__ rw2, const float* __restrict__ rb2){
    __shared__ float A[16*484];
    __shared__ float chs[16][22];
    __shared__ float dlg[16][22];
    __shared__ float trs[16];
    __shared__ float trm;
    int tid = threadIdx.x, w = tid >> 5, lane = tid & 31;
    float* a = A + w*484;
    if (lane < 22){
        float s = 0.f;
        #pragma unroll
        for (int c = 0; c < 16; c++) s += g_covp[w][c][253+lane];
        chs[w][lane] = s;
    }
    __syncwarp();
    for (int p = lane; p < 253; p += 32){
        int i=0,q=p; while (q >= 22-i){ q -= 22-i; i++; } int j = i+q;
        float s = 0.f;
        #pragma unroll
        for (int c = 0; c < 16; c++) s += g_covp[w][c][p];
        float cov = (s - chs[w][i]*chs[w][j]*(1.f/16000.f)) * (1.f/15999.f);
        if (i == j) cov += 1e-5f;
        a[i*22+j] = cov;
        a[j*22+i] = cov;
    }
    __syncwarp();
    if (lane == 0){ float tr=0.f; for (int k=0;k<22;k++) tr += a[k*22+k]; trs[w]=tr; }
    __syncthreads();
    if (tid == 0){ float s=0.f; for (int b=0;b<16;b++) s += trs[b]; trm = s*(0.001f/16.f); }
    __syncthreads();
    if (lane < 22) a[lane*22+lane] += trm;
    __syncwarp();
    for (int jj = 0; jj < 22; jj++){
        float dj = 0.f;
        if (lane == jj){ dj = sqrtf(a[jj*22+jj]); a[jj*22+jj] = dj; }
        dj = __shfl_sync(0xffffffffu, dj, jj);
        if (lane > jj && lane < 22) a[lane*22+jj] /= dj;
        __syncwarp();
        if (lane > jj && lane < 22){
            float lij = a[lane*22+jj];
            for (int k = jj+1; k <= lane; k++) a[lane*22+k] -= lij * a[k*22+jj];
        }
        __syncwarp();
    }
    if (lane < 22){
        float d = a[lane*22+lane];
        dlg[w][lane] = d * logf(fmaxf(d, 1e-10f));
    }
    __syncwarp();
    float hreg[8];
    #pragma unroll
    for (int m = 0; m < 8; m++){
        int h = lane + 32*m;
        float acc = rb1[h];
        #pragma unroll
        for (int i = 0; i < 22; i++){
            int pos = i*22 - (i*(i-1))/2;
            acc += dlg[w][i]*rw1[pos*256 + h];
        }
        hreg[m] = acc > 0.f ? acc : expm1f(acc);
    }
    __syncwarp();
    #pragma unroll
    for (int m = 0; m < 8; m++) a[lane + 32*m] = hreg[m];
    __syncwarp();
    for (int o = lane; o < 48; o += 32){
        float acc = rb2[o];
        #pragma unroll 8
        for (int k = 0; k < 256; k++) acc += a[k]*rw2[k*48+o];
        g_rfeat[w][o] = acc;
    }
}

// fused: channel-mix -> 64-tap FIR -> elu -> pool8 -> p1. grid(63,16), block 512
__global__ void __launch_bounds__(512, 2) k_conv1f(const float* __restrict__ x,
                                                   const float* __restrict__ dw1w,
                                                   const float* __restrict__ c1w){
    extern __shared__ float sm[];
    float* xs = sm;             // 22*322 = 7084
    float* ys = sm + 7084;      // 32*321 = 10272
    float* wT = sm + 17356;     // 22*34 = 748
    float* cws = sm + 18104;    // 16*65 = 1040  (total 19144 floats)
    int b = blockIdx.y, tid = threadIdx.x;
    int u0 = blockIdx.x*32;
    int T0 = u0*8;
    for (int idx = tid; idx < 22*320; idx += 512){
        int ch = idx/320, m = idx - ch*320;
        int t = T0 - 32 + m;
        xs[ch*322+m] = (t >= 0 && t < 16000) ? x[(b*22+ch)*16000 + t] : 0.f;
    }
    for (int idx = tid; idx < 704; idx += 512){
        int oc = idx/22, ch = idx - oc*22;
        wT[ch*34+oc] = dw1w[idx];
    }
    for (int idx = tid; idx < 1024; idx += 512){
        int ic = idx >> 6, k = idx & 63;
        cws[ic*65+k] = c1w[idx];
    }
    __syncthreads();
    for (int idx = tid; idx < 2560; idx += 512){
        int ocp = idx/160, mp = idx - ocp*160;
        int oc0 = ocp*2, m = mp*2;
        float a00=0.f, a01=0.f, a10=0.f, a11=0.f;
        #pragma unroll
        for (int ch = 0; ch < 22; ch++){
            float2 xv = *(const float2*)&xs[ch*322+m];
            float2 wv = *(const float2*)&wT[ch*34+oc0];
            a00 += wv.x*xv.x; a01 += wv.x*xv.y;
            a10 += wv.y*xv.x; a11 += wv.y*xv.y;
        }
        ys[oc0*321+m] = a00;   ys[oc0*321+m+1] = a01;
        ys[(oc0+1)*321+m] = a10; ys[(oc0+1)*321+m+1] = a11;
    }
    __syncthreads();
    int oc = tid & 31, grp = tid >> 5;
    const float* yrow = ys + oc*321;
    const float* cw = cws + (oc>>1)*65;
    #pragma unroll 1
    for (int s2 = 0; s2 < 2; s2++){
        int ul = grp*2 + s2;
        int u = u0 + ul;
        int base = 8*ul;
        float acc[8], yr[8];
        #pragma unroll
        for (int s = 0; s < 8; s++){ acc[s]=0.f; yr[s]=yrow[base+s]; }
        #pragma unroll 8
        for (int k = 0; k < 64; k++){
            float w = cw[k];
            #pragma unroll
            for (int s = 0; s < 8; s++) acc[s] += w*yr[s];
            #pragma unroll
            for (int m = 0; m < 7; m++) yr[m] = yr[m+1];
            yr[7] = yrow[base + k + 8];
        }
        if (u < 2000){
            float p = 0.f;
            #pragma unroll
            for (int s = 0; s < 8; s++) p += eluf(BN2F*acc[s]);
            g_p1[(b*32+oc)*2000 + u] = p*0.125f;
        }
    }
}

// dw2 -> pw -> elu -> pool8 -> featA. grid(32,16), block 128, 8 u per block.
__global__ void k_c2(const float* __restrict__ dw2w, const float* __restrict__ pww){
    __shared__ float p1s[32*81];
    __shared__ float qs[32*65];
    __shared__ float pwT[32*49];
    __shared__ float dwt[16*33];
    int b = blockIdx.y, tid = threadIdx.x;
    int u0 = blockIdx.x*8;
    int T0 = u0*8;
    for (int idx = tid; idx < 32*80; idx += 128){
        int oc = idx/80, m = idx - (idx/80)*80;
        int t = T0 - 8 + m;
        p1s[oc*81+m] = (t >= 0 && t < 2000) ? g_p1[(b*32+oc)*2000 + t] : 0.f;
    }
    for (int idx = tid; idx < 1536; idx += 128){
        int co = idx/32, ci = idx%32;
        pwT[ci*49+co] = pww[idx];
    }
    for (int idx = tid; idx < 512; idx += 128){
        int oc = idx/16, k = idx%16;
        dwt[k*33+oc] = dw2w[idx];
    }
    __syncthreads();
    for (int v = tid; v < 2048; v += 128){
        int oc = v & 31, t = v >> 5;
        float a = 0.f;
        #pragma unroll
        for (int k = 0; k < 16; k++) a += dwt[k*33+oc]*p1s[oc*81 + t + k];
        qs[oc*65+t] = a*BNF;
    }
    __syncthreads();
    {
        int cog = tid & 15, ul = tid >> 4;
        int u = u0 + ul;
        int co0 = cog*3;
        float acc[3][8];
        #pragma unroll
        for (int j = 0; j < 3; j++)
            #pragma unroll
            for (int s = 0; s < 8; s++) acc[j][s] = 0.f;
        #pragma unroll 4
        for (int ci = 0; ci < 32; ci++){
            float p0 = pwT[ci*49+co0];
            float p1 = pwT[ci*49+co0+1];
            float p2 = pwT[ci*49+co0+2];
            const float* qr = qs + ci*65 + 8*ul;
            #pragma unroll
            for (int s = 0; s < 8; s++){
                float q = qr[s];
                acc[0][s] += p0*q;
                acc[1][s] += p1*q;
                acc[2][s] += p2*q;
            }
        }
        if (u < 250){
            #pragma unroll
            for (int j = 0; j < 3; j++){
                float p = 0.f;
                #pragma unroll
                for (int s = 0; s < 8; s++) p += eluf(BNF*acc[j][s]);
                g_featA[(b*250+u)*48 + co0 + j] = p*0.125f;
            }
        }
    }
}

// temporal conv branch + residual -> featF. grid(4,16), block 256
__global__ void k_tc(const float* __restrict__ tc1w, const float* __restrict__ tc1b,
                     const float* __restrict__ tc2w, const float* __restrict__ tc2b){
    __shared__ float fa[66*48];
    __shared__ float t1s[24*64];
    int b = blockIdx.y, tid = threadIdx.x;
    int u0 = blockIdx.x*64;
    for (int idx = tid; idx < 66*48; idx += 256){
        int r = idx/48, co = idx%48;
        int u = u0 - 1 + r;
        fa[idx] = (u >= 0 && u < 250) ? g_featA[(b*250+u)*48 + co] : 0.f;
    }
    __syncthreads();
    for (int idx = tid; idx < 24*64; idx += 256){
        int g = idx/64, ul = idx%64;
        if (u0 + ul >= 250) continue;
        float a = tc1b[g];
        #pragma unroll
        for (int ci = 0; ci < 2; ci++)
            #pragma unroll
            for (int k = 0; k < 3; k++)
                a += tc1w[(g*2+ci)*3 + k] * fa[(ul+k)*48 + 2*g + ci];
        t1s[g*64+ul] = geluf(BNF*a);
    }
    __syncthreads();
    for (int idx = tid; idx < 48*64; idx += 256){
        int co = idx % 48, ul = idx / 48;
        int u = u0 + ul;
        if (u >= 250) continue;
        float a = tc2b[co];
        #pragma unroll
        for (int g = 0; g < 24; g++) a += tc2w[co*24+g]*t1s[g*64+ul];
        g_featF[(b*250+u)*48 + co] = fa[(ul+1)*48 + co] + a;
    }
}

// fusion proj + pos_enc. grid(251,16), block 48
__global__ void k_fuse(const float* __restrict__ fproj, const float* __restrict__ pe){
    __shared__ float r[48];
    int n = blockIdx.x, b = blockIdx.y, co = threadIdx.x;
    r[co] = (n == 0) ? g_rfeat[b][co] : g_featF[(b*250 + n - 1)*48 + co];
    __syncthreads();
    float a = pe[n*48 + co];
    #pragma unroll 8
    for (int k = 0; k < 48; k++) a += r[k]*fproj[k*48+co];
    g_fused[(b*251+n)*48 + co] = a;
}

// fused LN1 + QKV (4r x 2c float2 tile) + banded attention + out proj (2c float2) + residual.
__global__ void k_attnf(int l, const float* __restrict__ qw, const float* __restrict__ qb,
                        const float* __restrict__ g1, const float* __restrict__ b1,
                        const float* __restrict__ apw, const float* __restrict__ apb){
    extern __shared__ float sm[];
    float* wq  = sm;             // 6912
    float* qs  = sm + 6912;      // 3744
    float* xf  = sm + 10656;     // 1248
    float* hn  = sm + 11904;     // 1344 (28 rows, last 2 zero)
    float* wp  = sm + 13248;     // 2304
    float* os  = sm + 15552;     // 768
    float* sc  = sm + 16320;     // 1536
    float* qbs = sm + 17856;     // 144
    float* apbs= sm + 18000;     // 48   (total 18048 floats)
    int b = blockIdx.y, tid = threadIdx.x;
    int n0 = blockIdx.x*16;
    const float* wsrc = qw + l*48*144;
    for (int idx = tid; idx < 6912; idx += 256) wq[idx] = wsrc[idx];
    const float* psrc = apw + l*48*48;
    for (int idx = tid; idx < 2304; idx += 256) wp[idx] = psrc[idx];
    if (tid < 144) qbs[tid] = qb[l*144 + tid];
    if (tid < 48) apbs[tid] = apb[l*48 + tid];
    if (tid >= 160 && tid < 256) hn[26*48 + (tid - 160)] = 0.f;  // zero pad rows 26-27
    for (int idx = tid; idx < 26*48; idx += 256){
        int r = idx/48, c = idx - r*48;
        int n = n0 - 5 + r;
        xf[idx] = (n >= 0 && n < 251) ? g_fused[(b*251+n)*48 + c] : 0.f;
    }
    __syncthreads();
    {
        int wd = tid >> 5, lane = tid & 31;
        #pragma unroll
        for (int s = 0; s < 4; s++){
            int rl = wd*4 + s;
            if (rl < 26){
                float v0 = xf[rl*48 + lane];
                float v1 = (lane < 16) ? xf[rl*48 + 32 + lane] : 0.f;
                float sum = v0 + v1, sq = v0*v0 + v1*v1;
                #pragma unroll
                for (int o = 16; o; o >>= 1){
                    sum += __shfl_xor_sync(0xffffffffu, sum, o);
                    sq  += __shfl_xor_sync(0xffffffffu, sq, o);
                }
                float m = sum*(1.f/48.f);
                float rinv = rsqrtf(sq*(1.f/48.f) - m*m + 1e-5f);
                hn[rl*48 + lane] = (v0-m)*rinv*g1[l*48+lane] + b1[l*48+lane];
                if (lane < 16) hn[rl*48 + 32 + lane] = (v1-m)*rinv*g1[l*48+32+lane] + b1[l*48+32+lane];
            }
        }
    }
    __syncthreads();
    // qkv: 7 rowgroups(4 rows, padded to 28) x 72 colpairs = 504 items
    for (int idx = tid; idx < 504; idx += 256){
        int rg = idx/72, cp = idx - rg*72;
        int col0 = cp*2;
        int r0 = rg*4;
        float2 bv = *(const float2*)&qbs[col0];
        float2 a0 = bv, a1 = bv, a2 = bv, a3 = bv;
        const float2* wv2 = (const float2*)wq;
        const float* h0p = hn + r0*48;
        #pragma unroll 8
        for (int k = 0; k < 48; k++){
            float2 wv = wv2[k*72 + cp];
            float h0 = h0p[k], hh1 = h0p[48+k], h2 = h0p[96+k], h3 = h0p[144+k];
            a0.x += h0*wv.x;  a0.y += h0*wv.y;
            a1.x += hh1*wv.x; a1.y += hh1*wv.y;
            a2.x += h2*wv.x;  a2.y += h2*wv.y;
            a3.x += h3*wv.x;  a3.y += h3*wv.y;
        }
        qs[r0*144+col0] = a0.x;     qs[r0*144+col0+1] = a0.y;
        if (r0+1 < 26){ qs[(r0+1)*144+col0] = a1.x; qs[(r0+1)*144+col0+1] = a1.y; }
        if (r0+2 < 26){ qs[(r0+2)*144+col0] = a2.x; qs[(r0+2)*144+col0+1] = a2.y; }
        if (r0+3 < 26){ qs[(r0+3)*144+col0] = a3.x; qs[(r0+3)*144+col0+1] = a3.y; }
    }
    __syncthreads();
    for (int idx = tid; idx < 1408; idx += 256){
        int tl = idx/88, rem = idx - tl*88, h = rem/11, kk = rem - h*11;
        int n = n0 + tl;
        if (n >= 251) continue;
        int kpos = n - 5 + kk;
        if (kpos < 0 || kpos > 250) continue;
        int rq = tl + 5, rk = tl + kk;
        float s = 0.f;
        #pragma unroll
        for (int d = 0; d < 6; d++) s += qs[rq*144 + h*6 + d]*qs[rk*144 + 48 + h*6 + d];
        sc[(tl*8+h)*12 + kk] = s*ATT_SCALE;
    }
    __syncthreads();
    if (tid < 128){
        int tl = tid >> 3, h = tid & 7;
        int n = n0 + tl;
        if (n < 251){
            int klo = (n - 5 < 0) ? 5 - n : 0;
            int khi = (n + 5 > 250) ? 255 - n : 10;
            float mx = -1e30f;
            for (int kk = klo; kk <= khi; kk++) mx = fmaxf(mx, sc[(tl*8+h)*12+kk]);
            float ss = 0.f;
            for (int kk = klo; kk <= khi; kk++){ float e = __expf(sc[(tl*8+h)*12+kk]-mx); sc[(tl*8+h)*12+kk] = e; ss += e; }
            float inv = 1.f/ss;
            float o[6] = {0,0,0,0,0,0};
            for (int kk = klo; kk <= khi; kk++){
                float p = sc[(tl*8+h)*12+kk]*inv;
                int rk = tl + kk;
                #pragma unroll
                for (int d = 0; d < 6; d++) o[d] += p*qs[rk*144 + 96 + h*6 + d];
            }
            #pragma unroll
            for (int d = 0; d < 6; d++) os[tl*48 + h*6+d] = o[d];
        }
    }
    __syncthreads();
    // out proj: 16 rows x 24 colpairs = 384 items
    for (int idx = tid; idx < 384; idx += 256){
        int rl = idx/24, cp = idx - (idx/24)*24;
        int col0 = cp*2;
        int n = n0 + rl;
        if (n >= 251) continue;
        float2 acc = *(const float2*)&apbs[col0];
        const float2* wp2 = (const float2*)wp;
        const float* orow = os + rl*48;
        #pragma unroll 8
        for (int k = 0; k < 48; k++){
            float2 wv = wp2[k*24 + cp];
            float ov = orow[k];
            acc.x += ov*wv.x;
            acc.y += ov*wv.y;
        }
        g_attn[(b*251+n)*48 + col0]     = xf[(rl+5)*48 + col0]     + acc.x;
        g_attn[(b*251+n)*48 + col0 + 1] = xf[(rl+5)*48 + col0 + 1] + acc.y;
    }
}

// LN2 + FFN + residual. FFN1: 2r x 4c float4 tile (384 items = block). grid 251, block 384.
__global__ void k_ffn(int l, const float* __restrict__ fw1, const float* __restrict__ fb1,
                      const float* __restrict__ fw2, const float* __restrict__ fb2,
                      const float* __restrict__ g2, const float* __restrict__ bb2){
    extern __shared__ float dsm[];
    float* w1s = dsm;                 // 9216
    float* w2s = dsm + 9216;          // 9216
    float* hn  = dsm + 18432;         // 768
    float* h1  = dsm + 19200;         // 3072
    float* xs  = dsm + 22272;         // 768   (total 23040 floats)
    int r0 = blockIdx.x*16;
    int tid = threadIdx.x;
    const float* w1p = fw1 + l*48*192;
    const float* w2p = fw2 + l*192*48;
    for (int idx = tid; idx < 9216; idx += 384){ w1s[idx] = w1p[idx]; w2s[idx] = w2p[idx]; }
    int wd = tid >> 5, lane = tid & 31;
    if (wd < 8){
        #pragma unroll
        for (int s = 0; s < 2; s++){
            int rl = wd*2 + s;
            int row = r0 + rl;
            float v0 = g_attn[row*48 + lane];
            float v1 = (lane < 16) ? g_attn[row*48 + 32 + lane] : 0.f;
            float sum = v0 + v1, sq = v0*v0 + v1*v1;
            #pragma unroll
            for (int o = 16; o; o >>= 1){
                sum += __shfl_xor_sync(0xffffffffu, sum, o);
                sq  += __shfl_xor_sync(0xffffffffu, sq, o);
            }
            float m = sum*(1.f/48.f);
            float rinv = rsqrtf(sq*(1.f/48.f) - m*m + 1e-5f);
            xs[rl*48 + lane] = v0;
            hn[rl*48 + lane] = (v0-m)*rinv*g2[l*48+lane] + bb2[l*48+lane];
            if (lane < 16){
                xs[rl*48 + 32 + lane] = v1;
                hn[rl*48 + 32 + lane] = (v1-m)*rinv*g2[l*48+32+lane] + bb2[l*48+32+lane];
            }
        }
    }
    __syncthreads();
    // FFN1: 8 rowpairs x 48 colquads = 384 items
    {
        int rg = tid/48, cq = tid - (tid/48)*48;
        int col0 = cq*4;
        float4 bv = *(const float4*)&fb1[l*192 + col0];
        float4 a0 = bv, a1 = bv;
        const float4* w1v = (const float4*)w1s;
        const float* hp = hn + rg*2*48;
        #pragma unroll 8
        for (int k = 0; k < 48; k++){
            float4 wv = w1v[k*48 + cq];
            float h0 = hp[k], hh1 = hp[48+k];
            a0.x += h0*wv.x; a0.y += h0*wv.y; a0.z += h0*wv.z; a0.w += h0*wv.w;
            a1.x += hh1*wv.x; a1.y += hh1*wv.y; a1.z += hh1*wv.z; a1.w += hh1*wv.w;
        }
        float* d0 = h1 + (rg*2)*192 + col0;
        float* d1 = h1 + (rg*2+1)*192 + col0;
        d0[0] = geluf(a0.x); d0[1] = geluf(a0.y); d0[2] = geluf(a0.z); d0[3] = geluf(a0.w);
        d1[0] = geluf(a1.x); d1[1] = geluf(a1.y); d1[2] = geluf(a1.z); d1[3] = geluf(a1.w);
    }
    __syncthreads();
    // FFN2: 16 rows x 24 colpairs
    {
        int row = tid/24, cp = tid - (tid/24)*24;
        int col0 = cp*2;
        float2 acc = make_float2(fb2[l*48 + col0], fb2[l*48 + col0 + 1]);
        const float2* w2v = (const float2*)w2s;
        const float* hrow = h1 + row*192;
        #pragma unroll 4
        for (int k = 0; k < 192; k++){
            float2 wv = w2v[k*24 + cp];
            float hv = hrow[k];
            acc.x += hv*wv.x;
            acc.y += hv*wv.y;
        }
        int n = r0 + row;
        g_fused[n*48 + col0]     = xs[row*48 + col0]     + acc.x;
        g_fused[n*48 + col0 + 1] = xs[row*48 + col0 + 1] + acc.y;
    }
}

// mean over tokens + LN + classifier. grid 16, block 64
__global__ void k_head(const float* __restrict__ cg, const float* __restrict__ cb,
                       const float* __restrict__ cw, const float* __restrict__ cbias,
                       float* __restrict__ out){
    __shared__ float gm[48];
    int b = blockIdx.x, tid = threadIdx.x;
    if (tid < 48){
        float s = 0.f;
        for (int n = 0; n < 251; n++) s += g_fused[(b*251+n)*48 + tid];
        gm[tid] = s*(1.f/251.f);
    }
    __syncthreads();
    if (tid < 4){
        float m = 0.f;
        #pragma unroll 8
        for (int k = 0; k < 48; k++) m += gm[k];
        m *= (1.f/48.f);
        float v = 0.f;
        #pragma unroll 8
        for (int k = 0; k < 48; k++){ float d = gm[k]-m; v += d*d; }
        float rinv = rsqrtf(v*(1.f/48.f) + 1e-5f);
        float a = cbias[tid];
        #pragma unroll 8
        for (int k = 0; k < 48; k++){
            float gn = (gm[k]-m)*rinv*cg[k] + cb[k];
            a += gn*cw[k*4 + tid];
        }
        out[b*4 + tid] = a;
    }
}

#define CONV1F_SMEM (19144*4)
#define ATTNF_SMEM  (18048*4)
#define FFN_SMEM    (23040*4)

extern "C" void kernel_launch(void* const* d_in, const int* in_sizes, int n_in,
                              void* d_out, int out_size) {
    const float* x      = (const float*)d_in[0];
    const float* rw1    = (const float*)d_in[1];
    const float* rb1    = (const float*)d_in[2];
    const float* rw2    = (const float*)d_in[3];
    const float* rb2    = (const float*)d_in[4];
    const float* c1w    = (const float*)d_in[5];
    const float* dw1w   = (const float*)d_in[6];
    const float* dw2w   = (const float*)d_in[7];
    const float* pww    = (const float*)d_in[8];
    const float* tc1w   = (const float*)d_in[9];
    const float* tc1b   = (const float*)d_in[10];
    const float* tc2w   = (const float*)d_in[11];
    const float* tc2b   = (const float*)d_in[12];
    const float* fproj  = (const float*)d_in[13];
    const float* pe     = (const float*)d_in[14];
    const float* ln1g   = (const float*)d_in[15];
    const float* ln1b   = (const float*)d_in[16];
    const float* qkvw   = (const float*)d_in[17];
    const float* qkvb   = (const float*)d_in[18];
    const float* apw    = (const float*)d_in[19];
    const float* apb    = (const float*)d_in[20];
    const float* ln2g   = (const float*)d_in[21];
    const float* ln2b   = (const float*)d_in[22];
    const float* fw1    = (const float*)d_in[23];
    const float* fb1    = (const float*)d_in[24];
    const float* fw2    = (const float*)d_in[25];
    const float* fb2    = (const float*)d_in[26];
    const float* clsg   = (const float*)d_in[27];
    const float* clsb   = (const float*)d_in[28];
    const float* clsw   = (const float*)d_in[29];
    const float* clsbias= (const float*)d_in[30];
    float* out = (float*)d_out;

    static cudaStream_t s2 = nullptr;
    static cudaEvent_t eFork = nullptr, eJoin = nullptr;
    static int attr_set = 0;
    if (!attr_set){
        cudaFuncSetAttribute(k_conv1f, cudaFuncAttributeMaxDynamicSharedMemorySize, CONV1F_SMEM);
        cudaFuncSetAttribute(k_attnf,  cudaFuncAttributeMaxDynamicSharedMemorySize, ATTNF_SMEM);
        cudaFuncSetAttribute(k_ffn,    cudaFuncAttributeMaxDynamicSharedMemorySize, FFN_SMEM);
        cudaStreamCreateWithFlags(&s2, cudaStreamNonBlocking);
        cudaEventCreateWithFlags(&eFork, cudaEventDisableTiming);
        cudaEventCreateWithFlags(&eJoin, cudaEventDisableTiming);
        attr_set = 1;
    }

    // fork: SPD chain on s2, conv chain on default stream
    cudaEventRecord(eFork, 0);
    cudaStreamWaitEvent(s2, eFork, 0);
    k_covp<<<dim3(16,16), 288, 0, s2>>>(x);
    k_spd<<<1, 512, 0, s2>>>(rw1, rb1, rw2, rb2);
    cudaEventRecord(eJoin, s2);

    k_conv1f<<<dim3(63,16), 512, CONV1F_SMEM>>>(x, dw1w, c1w);
    k_c2<<<dim3(32,16), 128>>>(dw2w, pww);
    k_tc<<<dim3(4,16), 256>>>(tc1w, tc1b, tc2w, tc2b);

    // join before fusion
    cudaStreamWaitEvent(0, eJoin, 0);
    k_fuse<<<dim3(251,16), 48>>>(fproj, pe);
    for (int l = 0; l < 4; l++){
        k_attnf<<<dim3(16,16), 256, ATTNF_SMEM>>>(l, qkvw, qkvb, ln1g, ln1b, apw, apb);
        k_ffn<<<251, 384, FFN_SMEM>>>(l, fw1, fb1, fw2, fb2, ln2g, ln2b);
    }
    k_head<<<16, 64>>>(clsg, clsb, clsw, clsbias, out);
}